// round 1
// baseline (speedup 1.0000x reference)
#include <cuda_runtime.h>

#define Bb   4
#define Ss   2048
#define HIDD 1024
#define Hh   16
#define Dd   64
#define M_TOT (Bb*Ss)   // 8192

// Scratch (static device globals: allocation-free)
__device__ float g_Q[(size_t)M_TOT*HIDD];
__device__ float g_K[(size_t)M_TOT*HIDD];
__device__ float g_V[(size_t)M_TOT*HIDD];
__device__ float g_O[(size_t)M_TOT*HIDD];

// ---------------------------------------------------------------------------
// SGEMM: C[M,N] = A[M,K] @ B[K,N], row-major. M%128==0, N%128==0, K%8==0.
// 128x128 block tile, BK=8, 8x8 per-thread microtile, 256 threads.
// ---------------------------------------------------------------------------
#define GBM 128
#define GBN 128
#define GBK 8
#define GTM 8
#define GTN 8

__global__ __launch_bounds__(256) void sgemm_kernel(
    const float* __restrict__ A, const float* __restrict__ B,
    float* __restrict__ C, int M, int N, int K)
{
    __shared__ float As[GBK][GBM];
    __shared__ float Bs[GBK][GBN];

    const int tid  = threadIdx.x;
    const int row0 = blockIdx.y * GBM;
    const int col0 = blockIdx.x * GBN;

    const int aRow = tid >> 1;          // 0..127
    const int aCol = (tid & 1) * 4;     // 0 or 4
    const int bRow = tid >> 5;          // 0..7
    const int bCol = (tid & 31) * 4;    // 0..124

    const int tx = tid & 15;
    const int ty = tid >> 4;

    float acc[GTM][GTN] = {};

    const float* Ap = A + (size_t)(row0 + aRow) * K + aCol;
    const float* Bp = B + (size_t)bRow * N + col0 + bCol;

    for (int k0 = 0; k0 < K; k0 += GBK) {
        float4 a4 = *(const float4*)(Ap + k0);
        As[aCol+0][aRow] = a4.x;
        As[aCol+1][aRow] = a4.y;
        As[aCol+2][aRow] = a4.z;
        As[aCol+3][aRow] = a4.w;
        *(float4*)&Bs[bRow][bCol] = *(const float4*)(Bp + (size_t)k0 * N);
        __syncthreads();

        #pragma unroll
        for (int kk = 0; kk < GBK; kk++) {
            float4 ra0 = *(float4*)&As[kk][ty*GTM];
            float4 ra1 = *(float4*)&As[kk][ty*GTM+4];
            float4 rb0 = *(float4*)&Bs[kk][tx*GTN];
            float4 rb1 = *(float4*)&Bs[kk][tx*GTN+4];
            float ra[GTM] = {ra0.x,ra0.y,ra0.z,ra0.w, ra1.x,ra1.y,ra1.z,ra1.w};
            float rb[GTN] = {rb0.x,rb0.y,rb0.z,rb0.w, rb1.x,rb1.y,rb1.z,rb1.w};
            #pragma unroll
            for (int i = 0; i < GTM; i++)
                #pragma unroll
                for (int j = 0; j < GTN; j++)
                    acc[i][j] += ra[i] * rb[j];
        }
        __syncthreads();
    }

    #pragma unroll
    for (int i = 0; i < GTM; i++) {
        float* Cp = C + (size_t)(row0 + ty*GTM + i) * N + col0 + tx*GTN;
        *(float4*)(Cp + 0) = make_float4(acc[i][0], acc[i][1], acc[i][2], acc[i][3]);
        *(float4*)(Cp + 4) = make_float4(acc[i][4], acc[i][5], acc[i][6], acc[i][7]);
    }
}

// ---------------------------------------------------------------------------
// Fused flash attention, fp32.
// Block = one (b, h, 64-query tile). 256 threads as 16(tx) x 16(ty).
// Thread owns 4 query rows (4*ty+i) x 4 key cols / 4 out dims (4*tx+j).
// Q is pre-scaled by (1/sqrt(D)) * log2(e) so softmax uses a single EX2.
// ---------------------------------------------------------------------------
#define BQ  64
#define BK  64
#define PAD 68     // row stride in floats (keeps float4 alignment, breaks conflicts)

__global__ __launch_bounds__(256) void attn_kernel()
{
    extern __shared__ float sm[];
    float* Qt = sm;               // [Dd][PAD]  d-major, col = query
    float* Kt = sm + 64*PAD;      // [Dd][PAD]  d-major, col = key
    float* Vs = sm + 2*64*PAD;    // [BK][PAD]  key-major, col = dim
    float* Pt = sm + 3*64*PAD;    // [BK][PAD]  key-major, col = query

    const int tid = threadIdx.x;
    const int tx  = tid & 15;
    const int ty  = tid >> 4;
    const int q0  = blockIdx.x * BQ;
    const int h   = blockIdx.y;
    const int b   = blockIdx.z;

    const float qscale = 0.125f * 1.44269504088896340736f; // 1/sqrt(64) * log2(e)

    // ---- load Q tile, transposed + scaled ----
    {
        const size_t qbase = ((size_t)(b*Ss + q0))*HIDD + h*Dd;
        #pragma unroll
        for (int it = 0; it < 4; it++) {
            int idx = it*256 + tid;
            int row = idx >> 4;          // query in tile
            int d4  = (idx & 15) * 4;    // dim
            float4 qv = *(const float4*)(g_Q + qbase + (size_t)row*HIDD + d4);
            Qt[(d4+0)*PAD + row] = qv.x * qscale;
            Qt[(d4+1)*PAD + row] = qv.y * qscale;
            Qt[(d4+2)*PAD + row] = qv.z * qscale;
            Qt[(d4+3)*PAD + row] = qv.w * qscale;
        }
    }

    float m_i[4], l_i[4], acc[4][4];
    #pragma unroll
    for (int i = 0; i < 4; i++) {
        m_i[i] = -1e30f; l_i[i] = 0.0f;
        #pragma unroll
        for (int j = 0; j < 4; j++) acc[i][j] = 0.0f;
    }

    for (int kt = 0; kt < Ss/BK; kt++) {
        // ---- load K (transposed) and V tiles ----
        const size_t kbase = ((size_t)(b*Ss + kt*BK))*HIDD + h*Dd;
        __syncthreads();   // protect Kt/Vs/Pt from previous iteration's readers
        #pragma unroll
        for (int it = 0; it < 4; it++) {
            int idx = it*256 + tid;
            int row = idx >> 4;
            int d4  = (idx & 15) * 4;
            float4 kv = *(const float4*)(g_K + kbase + (size_t)row*HIDD + d4);
            Kt[(d4+0)*PAD + row] = kv.x;
            Kt[(d4+1)*PAD + row] = kv.y;
            Kt[(d4+2)*PAD + row] = kv.z;
            Kt[(d4+3)*PAD + row] = kv.w;
            float4 vv = *(const float4*)(g_V + kbase + (size_t)row*HIDD + d4);
            *(float4*)&Vs[row*PAD + d4] = vv;
        }
        __syncthreads();

        // ---- S = (Q*scale*log2e) @ K^T ----
        float s[4][4] = {};
        #pragma unroll 8
        for (int d = 0; d < Dd; d++) {
            float4 qa = *(float4*)&Qt[d*PAD + 4*ty];
            float4 kb = *(float4*)&Kt[d*PAD + 4*tx];
            float ra[4] = {qa.x, qa.y, qa.z, qa.w};
            float rb[4] = {kb.x, kb.y, kb.z, kb.w};
            #pragma unroll
            for (int i = 0; i < 4; i++)
                #pragma unroll
                for (int j = 0; j < 4; j++)
                    s[i][j] += ra[i] * rb[j];
        }

        // ---- online softmax (base-2) ----
        float alpha[4];
        #pragma unroll
        for (int i = 0; i < 4; i++) {
            float mx = fmaxf(fmaxf(s[i][0], s[i][1]), fmaxf(s[i][2], s[i][3]));
            #pragma unroll
            for (int off = 8; off > 0; off >>= 1)
                mx = fmaxf(mx, __shfl_xor_sync(0xffffffffu, mx, off));
            float newm = fmaxf(m_i[i], mx);
            alpha[i] = exp2f(m_i[i] - newm);
            m_i[i] = newm;
            float sum = 0.0f;
            #pragma unroll
            for (int j = 0; j < 4; j++) {
                s[i][j] = exp2f(s[i][j] - newm);
                sum += s[i][j];
            }
            #pragma unroll
            for (int off = 8; off > 0; off >>= 1)
                sum += __shfl_xor_sync(0xffffffffu, sum, off);
            l_i[i] = l_i[i] * alpha[i] + sum;
        }

        // ---- stash P (key-major), rescale accumulator ----
        #pragma unroll
        for (int i = 0; i < 4; i++) {
            #pragma unroll
            for (int j = 0; j < 4; j++) {
                Pt[(4*tx+j)*PAD + 4*ty + i] = s[i][j];
                acc[i][j] *= alpha[i];
            }
        }
        __syncthreads();

        // ---- O += P @ V ----
        #pragma unroll 8
        for (int k = 0; k < BK; k++) {
            float4 pa = *(float4*)&Pt[k*PAD + 4*ty];
            float4 vb = *(float4*)&Vs[k*PAD + 4*tx];
            float ra[4] = {pa.x, pa.y, pa.z, pa.w};
            float rb[4] = {vb.x, vb.y, vb.z, vb.w};
            #pragma unroll
            for (int i = 0; i < 4; i++)
                #pragma unroll
                for (int j = 0; j < 4; j++)
                    acc[i][j] += ra[i] * rb[j];
        }
    }

    // ---- normalize + write O tile ----
    #pragma unroll
    for (int i = 0; i < 4; i++) {
        float inv = 1.0f / l_i[i];
        float4 o = make_float4(acc[i][0]*inv, acc[i][1]*inv, acc[i][2]*inv, acc[i][3]*inv);
        *(float4*)&g_O[((size_t)(b*Ss + q0 + 4*ty + i))*HIDD + h*Dd + 4*tx] = o;
    }
}

// ---------------------------------------------------------------------------
extern "C" void kernel_launch(void* const* d_in, const int* in_sizes, int n_in,
                              void* d_out, int out_size)
{
    (void)in_sizes; (void)n_in; (void)out_size;
    const float* q  = (const float*)d_in[0];
    const float* k  = (const float*)d_in[1];
    const float* v  = (const float*)d_in[2];
    const float* Wq = (const float*)d_in[3];
    const float* Wk = (const float*)d_in[4];
    const float* Wv = (const float*)d_in[5];
    const float* Wo = (const float*)d_in[6];
    float* out = (float*)d_out;

    float *pQ, *pK, *pV, *pO;
    cudaGetSymbolAddress((void**)&pQ, g_Q);
    cudaGetSymbolAddress((void**)&pK, g_K);
    cudaGetSymbolAddress((void**)&pV, g_V);
    cudaGetSymbolAddress((void**)&pO, g_O);

    const dim3 gg(HIDD/GBN, M_TOT/GBM);   // (8, 64)
    sgemm_kernel<<<gg, 256>>>(q, Wq, pQ, M_TOT, HIDD, HIDD);
    sgemm_kernel<<<gg, 256>>>(k, Wk, pK, M_TOT, HIDD, HIDD);
    sgemm_kernel<<<gg, 256>>>(v, Wv, pV, M_TOT, HIDD, HIDD);

    const int attn_smem = 4 * 64 * PAD * (int)sizeof(float);  // 69632 B
    cudaFuncSetAttribute(attn_kernel,
                         cudaFuncAttributeMaxDynamicSharedMemorySize, attn_smem);
    attn_kernel<<<dim3(Ss/BQ, Hh, Bb), 256, attn_smem>>>();

    sgemm_kernel<<<gg, 256>>>(pO, Wo, out, M_TOT, HIDD, HIDD);
}

// round 3
// speedup vs baseline: 1.4064x; 1.4064x over previous
#include <cuda_runtime.h>
#include <cuda_bf16.h>
#include <cstdint>

#define Bb   4
#define Ss   2048
#define HIDD 1024
#define Hh   16
#define Dd   64
#define M_TOT (Bb*Ss)   // 8192

// ---------------- scratch (static device globals; allocation-free) ----------
__device__ float g_Q[(size_t)M_TOT*HIDD];
__device__ float g_K[(size_t)M_TOT*HIDD];
__device__ float g_V[(size_t)M_TOT*HIDD];
__device__ float g_O[(size_t)M_TOT*HIDD];
__device__ __nv_bfloat16 g_Ahi[(size_t)M_TOT*HIDD];
__device__ __nv_bfloat16 g_Alo[(size_t)M_TOT*HIDD];
__device__ __nv_bfloat16 g_Whi[(size_t)HIDD*HIDD];   // [N,K] transposed
__device__ __nv_bfloat16 g_Wlo[(size_t)HIDD*HIDD];

// ---------------- helpers ----------------------------------------------------
__device__ __forceinline__ uint32_t smem_u32(const void* p) {
    return (uint32_t)__cvta_generic_to_shared(p);
}
#define CP16(dst,src)  asm volatile("cp.async.cg.shared.global [%0], [%1], 16;" :: "r"(dst), "l"(src) : "memory")
#define CP_COMMIT()    asm volatile("cp.async.commit_group;" ::: "memory")
#define CP_WAIT0()     asm volatile("cp.async.wait_group 0;" ::: "memory")

#define LDSM4(r0,r1,r2,r3,a) \
    asm volatile("ldmatrix.sync.aligned.m8n8.x4.shared.b16 {%0,%1,%2,%3}, [%4];" \
                 : "=r"(r0), "=r"(r1), "=r"(r2), "=r"(r3) : "r"(a))

#define MMA16816(d,a,b) \
    asm volatile("mma.sync.aligned.m16n8k16.row.col.f32.bf16.bf16.f32 " \
                 "{%0,%1,%2,%3}, {%4,%5,%6,%7}, {%8,%9}, {%0,%1,%2,%3};" \
                 : "+f"((d)[0]), "+f"((d)[1]), "+f"((d)[2]), "+f"((d)[3]) \
                 : "r"((a)[0]), "r"((a)[1]), "r"((a)[2]), "r"((a)[3]), \
                   "r"((b)[0]), "r"((b)[1]))

// ---------------- conversion kernels ----------------------------------------
__global__ __launch_bounds__(256) void cvt_act(const float4* __restrict__ x,
                                               __nv_bfloat162* __restrict__ hi,
                                               __nv_bfloat162* __restrict__ lo, int n4) {
    int i = blockIdx.x * blockDim.x + threadIdx.x;
    if (i >= n4) return;
    float4 v = x[i];
    __nv_bfloat16 h0 = __float2bfloat16(v.x), h1 = __float2bfloat16(v.y);
    __nv_bfloat16 h2 = __float2bfloat16(v.z), h3 = __float2bfloat16(v.w);
    __nv_bfloat16 l0 = __float2bfloat16(v.x - __bfloat162float(h0));
    __nv_bfloat16 l1 = __float2bfloat16(v.y - __bfloat162float(h1));
    __nv_bfloat16 l2 = __float2bfloat16(v.z - __bfloat162float(h2));
    __nv_bfloat16 l3 = __float2bfloat16(v.w - __bfloat162float(h3));
    hi[2*i]   = __halves2bfloat162(h0, h1);
    hi[2*i+1] = __halves2bfloat162(h2, h3);
    lo[2*i]   = __halves2bfloat162(l0, l1);
    lo[2*i+1] = __halves2bfloat162(l2, l3);
}

// W [K,N] fp32 -> hi/lo [N,K] bf16 (transpose)
__global__ __launch_bounds__(256) void cvt_wT(const float* __restrict__ W,
                                              __nv_bfloat16* __restrict__ hi,
                                              __nv_bfloat16* __restrict__ lo) {
    __shared__ float t[32][33];
    int n0 = blockIdx.x * 32, k0 = blockIdx.y * 32;
    int tx = threadIdx.x, ty = threadIdx.y;   // 32 x 8
    #pragma unroll
    for (int i = 0; i < 32; i += 8)
        t[ty + i][tx] = W[(size_t)(k0 + ty + i) * HIDD + n0 + tx];
    __syncthreads();
    #pragma unroll
    for (int i = 0; i < 32; i += 8) {
        float v = t[tx][ty + i];
        __nv_bfloat16 h = __float2bfloat16(v);
        __nv_bfloat16 l = __float2bfloat16(v - __bfloat162float(h));
        size_t o = (size_t)(n0 + ty + i) * HIDD + k0 + tx;
        hi[o] = h; lo[o] = l;
    }
}

// ---------------- mma.sync bf16x3 GEMM ---------------------------------------
// C[M,N] = A[M,K] @ W[K,N];  A given as hi/lo [M,K], W^T as hi/lo [N,K].
// CTA 128x128, BK=32, double-buffered cp.async. 8 warps: 4(M) x 2(N), 32x64.
#define KTOT 1024
#define GBK  32
#define NSTG (KTOT/GBK)
#define BSTR 40                       // smem row stride, elements (80 B)
#define TILE_B (128*BSTR*2)           // 10240 B per operand tile
#define STG_B  (4*TILE_B)             // 40960 B per stage
#define GEMM_SMEM (2*STG_B)           // 81920 B

__global__ __launch_bounds__(256) void gemm_kernel(
    const __nv_bfloat16* __restrict__ Ahi, const __nv_bfloat16* __restrict__ Alo,
    const __nv_bfloat16* __restrict__ Bhi, const __nv_bfloat16* __restrict__ Blo,
    float* __restrict__ C)
{
    extern __shared__ char smraw[];
    const uint32_t sb = smem_u32(smraw);
    const int tid = threadIdx.x;
    const int wid = tid >> 5, lane = tid & 31;
    const int m0 = blockIdx.y * 128;
    const int n0 = blockIdx.x * 128;
    const int wm = (wid & 3) * 32;       // warp M offset
    const int wn = (wid >> 2) * 64;      // warp N offset

    // global bases (bytes)
    const char* gA_hi = (const char*)(Ahi + (size_t)m0 * KTOT);
    const char* gA_lo = (const char*)(Alo + (size_t)m0 * KTOT);
    const char* gB_hi = (const char*)(Bhi + (size_t)n0 * KTOT);
    const char* gB_lo = (const char*)(Blo + (size_t)n0 * KTOT);

    // stage loader: 4 tiles, each 128 rows x 64B (padded to 80B rows)
    auto load_stage = [&](int it, int s) {
        const uint32_t stg = sb + (uint32_t)s * STG_B;
        const size_t kb = (size_t)it * GBK * 2;           // byte offset along K
        const char* srcs[4] = { gA_hi + kb, gA_lo + kb, gB_hi + kb, gB_lo + kb };
        #pragma unroll
        for (int op = 0; op < 4; op++) {
            const char* g = srcs[op];
            const uint32_t tb = stg + (uint32_t)op * TILE_B;
            #pragma unroll
            for (int j = 0; j < 2; j++) {
                int chunk = j * 256 + tid;     // 512 chunks = 128 rows x 4
                int r = chunk >> 2, c = chunk & 3;
                CP16(tb + (uint32_t)(r * 80 + c * 16),
                     g + (size_t)r * (KTOT * 2) + c * 16);
            }
        }
        CP_COMMIT();
    };

    // ldmatrix lane addressing (within a tile, before k16 offset)
    // A frag (16x16): lanes 0-15 -> row l, khalf 0; lanes 16-31 -> row l-16, khalf 1
    const uint32_t a_off = (uint32_t)((lane & 15) * 80 + (lane >> 4) * 16);
    // B frag pair (2 n-blocks x k16): n = ((l>>4)&1)*8 + (l&7), khalf = (l>>3)&1
    const uint32_t b_off = (uint32_t)((((lane >> 4) & 1) * 8 + (lane & 7)) * 80 +
                                      ((lane >> 3) & 1) * 16);

    float acc[2][8][4];
    #pragma unroll
    for (int mi = 0; mi < 2; mi++)
        #pragma unroll
        for (int ni = 0; ni < 8; ni++)
            #pragma unroll
            for (int r = 0; r < 4; r++) acc[mi][ni][r] = 0.0f;

    load_stage(0, 0);

    #pragma unroll 1
    for (int it = 0; it < NSTG; it++) {
        const int s = it & 1;
        CP_WAIT0();
        __syncthreads();
        if (it + 1 < NSTG) load_stage(it + 1, 1 - s);

        const uint32_t stg = sb + (uint32_t)s * STG_B;
        const uint32_t tAhi = stg;
        const uint32_t tAlo = stg + TILE_B;
        const uint32_t tBhi = stg + 2 * TILE_B;
        const uint32_t tBlo = stg + 3 * TILE_B;

        #pragma unroll
        for (int kk = 0; kk < 2; kk++) {          // two k16 steps per stage
            const uint32_t koff = (uint32_t)kk * 32;   // 16 elts = 32 B

            uint32_t ah[2][4], al[2][4];
            #pragma unroll
            for (int mi = 0; mi < 2; mi++) {
                uint32_t ra = (uint32_t)((wm + mi * 16) * 80) + a_off + koff;
                LDSM4(ah[mi][0], ah[mi][1], ah[mi][2], ah[mi][3], tAhi + ra);
                LDSM4(al[mi][0], al[mi][1], al[mi][2], al[mi][3], tAlo + ra);
            }

            uint32_t bh[8][2];
            #pragma unroll
            for (int j = 0; j < 4; j++) {         // pairs of n-blocks
                uint32_t rb = (uint32_t)((wn + j * 16) * 80) + b_off + koff;
                LDSM4(bh[2*j][0], bh[2*j][1], bh[2*j+1][0], bh[2*j+1][1], tBhi + rb);
            }
            #pragma unroll
            for (int mi = 0; mi < 2; mi++)
                #pragma unroll
                for (int ni = 0; ni < 8; ni++) {
                    MMA16816(acc[mi][ni], ah[mi], bh[ni]);   // hi*hi
                }
            #pragma unroll
            for (int mi = 0; mi < 2; mi++)
                #pragma unroll
                for (int ni = 0; ni < 8; ni++) {
                    MMA16816(acc[mi][ni], al[mi], bh[ni]);   // lo*hi
                }
            #pragma unroll
            for (int j = 0; j < 4; j++) {         // reload as Blo
                uint32_t rb = (uint32_t)((wn + j * 16) * 80) + b_off + koff;
                LDSM4(bh[2*j][0], bh[2*j][1], bh[2*j+1][0], bh[2*j+1][1], tBlo + rb);
            }
            #pragma unroll
            for (int mi = 0; mi < 2; mi++)
                #pragma unroll
                for (int ni = 0; ni < 8; ni++) {
                    MMA16816(acc[mi][ni], ah[mi], bh[ni]);   // hi*lo
                }
        }
        __syncthreads();
    }

    // epilogue: direct fp32 stores
    const int r_in = lane >> 2;
    const int c_in = (lane & 3) * 2;
    #pragma unroll
    for (int mi = 0; mi < 2; mi++) {
        #pragma unroll
        for (int ni = 0; ni < 8; ni++) {
            float* p0 = C + (size_t)(m0 + wm + mi * 16 + r_in) * HIDD + n0 + wn + ni * 8 + c_in;
            float* p1 = p0 + 8 * HIDD;
            *(float2*)p0 = make_float2(acc[mi][ni][0], acc[mi][ni][1]);
            *(float2*)p1 = make_float2(acc[mi][ni][2], acc[mi][ni][3]);
        }
    }
}

// ---------------- fused flash attention, fp32 (R1, proven) ------------------
#define BQ  64
#define BK  64
#define PAD 68

__global__ __launch_bounds__(256) void attn_kernel()
{
    extern __shared__ float smf[];
    float* Qt = smf;
    float* Kt = smf + 64*PAD;
    float* Vs = smf + 2*64*PAD;
    float* Pt = smf + 3*64*PAD;

    const int tid = threadIdx.x;
    const int tx  = tid & 15;
    const int ty  = tid >> 4;
    const int q0  = blockIdx.x * BQ;
    const int h   = blockIdx.y;
    const int b   = blockIdx.z;

    const float qscale = 0.125f * 1.44269504088896340736f;

    {
        const size_t qbase = ((size_t)(b*Ss + q0))*HIDD + h*Dd;
        #pragma unroll
        for (int it = 0; it < 4; it++) {
            int idx = it*256 + tid;
            int row = idx >> 4;
            int d4  = (idx & 15) * 4;
            float4 qv = *(const float4*)(g_Q + qbase + (size_t)row*HIDD + d4);
            Qt[(d4+0)*PAD + row] = qv.x * qscale;
            Qt[(d4+1)*PAD + row] = qv.y * qscale;
            Qt[(d4+2)*PAD + row] = qv.z * qscale;
            Qt[(d4+3)*PAD + row] = qv.w * qscale;
        }
    }

    float m_i[4], l_i[4], acc[4][4];
    #pragma unroll
    for (int i = 0; i < 4; i++) {
        m_i[i] = -1e30f; l_i[i] = 0.0f;
        #pragma unroll
        for (int j = 0; j < 4; j++) acc[i][j] = 0.0f;
    }

    for (int kt = 0; kt < Ss/BK; kt++) {
        const size_t kbase = ((size_t)(b*Ss + kt*BK))*HIDD + h*Dd;
        __syncthreads();
        #pragma unroll
        for (int it = 0; it < 4; it++) {
            int idx = it*256 + tid;
            int row = idx >> 4;
            int d4  = (idx & 15) * 4;
            float4 kv = *(const float4*)(g_K + kbase + (size_t)row*HIDD + d4);
            Kt[(d4+0)*PAD + row] = kv.x;
            Kt[(d4+1)*PAD + row] = kv.y;
            Kt[(d4+2)*PAD + row] = kv.z;
            Kt[(d4+3)*PAD + row] = kv.w;
            float4 vv = *(const float4*)(g_V + kbase + (size_t)row*HIDD + d4);
            *(float4*)&Vs[row*PAD + d4] = vv;
        }
        __syncthreads();

        float s[4][4] = {};
        #pragma unroll 8
        for (int d = 0; d < Dd; d++) {
            float4 qa = *(float4*)&Qt[d*PAD + 4*ty];
            float4 kb = *(float4*)&Kt[d*PAD + 4*tx];
            float ra[4] = {qa.x, qa.y, qa.z, qa.w};
            float rb[4] = {kb.x, kb.y, kb.z, kb.w};
            #pragma unroll
            for (int i = 0; i < 4; i++)
                #pragma unroll
                for (int j = 0; j < 4; j++)
                    s[i][j] += ra[i] * rb[j];
        }

        float alpha[4];
        #pragma unroll
        for (int i = 0; i < 4; i++) {
            float mx = fmaxf(fmaxf(s[i][0], s[i][1]), fmaxf(s[i][2], s[i][3]));
            #pragma unroll
            for (int off = 8; off > 0; off >>= 1)
                mx = fmaxf(mx, __shfl_xor_sync(0xffffffffu, mx, off));
            float newm = fmaxf(m_i[i], mx);
            alpha[i] = exp2f(m_i[i] - newm);
            m_i[i] = newm;
            float sum = 0.0f;
            #pragma unroll
            for (int j = 0; j < 4; j++) {
                s[i][j] = exp2f(s[i][j] - newm);
                sum += s[i][j];
            }
            #pragma unroll
            for (int off = 8; off > 0; off >>= 1)
                sum += __shfl_xor_sync(0xffffffffu, sum, off);
            l_i[i] = l_i[i] * alpha[i] + sum;
        }

        #pragma unroll
        for (int i = 0; i < 4; i++) {
            #pragma unroll
            for (int j = 0; j < 4; j++) {
                Pt[(4*tx+j)*PAD + 4*ty + i] = s[i][j];
                acc[i][j] *= alpha[i];
            }
        }
        __syncthreads();

        #pragma unroll 8
        for (int k = 0; k < BK; k++) {
            float4 pa = *(float4*)&Pt[k*PAD + 4*ty];
            float4 vb = *(float4*)&Vs[k*PAD + 4*tx];
            float ra[4] = {pa.x, pa.y, pa.z, pa.w};
            float rb[4] = {vb.x, vb.y, vb.z, vb.w};
            #pragma unroll
            for (int i = 0; i < 4; i++)
                #pragma unroll
                for (int j = 0; j < 4; j++)
                    acc[i][j] += ra[i] * rb[j];
        }
    }

    #pragma unroll
    for (int i = 0; i < 4; i++) {
        float inv = 1.0f / l_i[i];
        float4 o = make_float4(acc[i][0]*inv, acc[i][1]*inv, acc[i][2]*inv, acc[i][3]*inv);
        *(float4*)&g_O[((size_t)(b*Ss + q0 + 4*ty + i))*HIDD + h*Dd + 4*tx] = o;
    }
}

// ---------------------------------------------------------------------------
extern "C" void kernel_launch(void* const* d_in, const int* in_sizes, int n_in,
                              void* d_out, int out_size)
{
    (void)in_sizes; (void)n_in; (void)out_size;
    const float* q  = (const float*)d_in[0];
    const float* k  = (const float*)d_in[1];
    const float* v  = (const float*)d_in[2];
    const float* Wq = (const float*)d_in[3];
    const float* Wk = (const float*)d_in[4];
    const float* Wv = (const float*)d_in[5];
    const float* Wo = (const float*)d_in[6];
    float* out = (float*)d_out;

    float *pQ, *pK, *pV, *pO;
    __nv_bfloat16 *pAhi, *pAlo, *pWhi, *pWlo;
    cudaGetSymbolAddress((void**)&pQ, g_Q);
    cudaGetSymbolAddress((void**)&pK, g_K);
    cudaGetSymbolAddress((void**)&pV, g_V);
    cudaGetSymbolAddress((void**)&pO, g_O);
    cudaGetSymbolAddress((void**)&pAhi, g_Ahi);
    cudaGetSymbolAddress((void**)&pAlo, g_Alo);
    cudaGetSymbolAddress((void**)&pWhi, g_Whi);
    cudaGetSymbolAddress((void**)&pWlo, g_Wlo);

    cudaFuncSetAttribute(gemm_kernel, cudaFuncAttributeMaxDynamicSharedMemorySize, GEMM_SMEM);
    const int attn_smem = 4 * 64 * PAD * (int)sizeof(float);
    cudaFuncSetAttribute(attn_kernel, cudaFuncAttributeMaxDynamicSharedMemorySize, attn_smem);

    const int n4 = (M_TOT * HIDD) / 4;
    const dim3 cvtg(n4 / 256);
    const dim3 wtg(HIDD/32, HIDD/32), wtb(32, 8);
    const dim3 gg(HIDD/128, M_TOT/128);   // (8, 64)

    // Q projection
    cvt_act<<<cvtg, 256>>>((const float4*)q, (__nv_bfloat162*)pAhi, (__nv_bfloat162*)pAlo, n4);
    cvt_wT<<<wtg, wtb>>>(Wq, pWhi, pWlo);
    gemm_kernel<<<gg, 256, GEMM_SMEM>>>(pAhi, pAlo, pWhi, pWlo, pQ);
    // K projection
    cvt_act<<<cvtg, 256>>>((const float4*)k, (__nv_bfloat162*)pAhi, (__nv_bfloat162*)pAlo, n4);
    cvt_wT<<<wtg, wtb>>>(Wk, pWhi, pWlo);
    gemm_kernel<<<gg, 256, GEMM_SMEM>>>(pAhi, pAlo, pWhi, pWlo, pK);
    // V projection
    cvt_act<<<cvtg, 256>>>((const float4*)v, (__nv_bfloat162*)pAhi, (__nv_bfloat162*)pAlo, n4);
    cvt_wT<<<wtg, wtb>>>(Wv, pWhi, pWlo);
    gemm_kernel<<<gg, 256, GEMM_SMEM>>>(pAhi, pAlo, pWhi, pWlo, pV);

    // attention
    attn_kernel<<<dim3(Ss/BQ, Hh, Bb), 256, attn_smem>>>();

    // output projection
    cvt_act<<<cvtg, 256>>>((const float4*)pO, (__nv_bfloat162*)pAhi, (__nv_bfloat162*)pAlo, n4);
    cvt_wT<<<wtg, wtb>>>(Wo, pWhi, pWlo);
    gemm_kernel<<<gg, 256, GEMM_SMEM>>>(pAhi, pAlo, pWhi, pWlo, out);
}

// round 4
// speedup vs baseline: 2.8385x; 2.0183x over previous
#include <cuda_runtime.h>
#include <cuda_bf16.h>
#include <cstdint>

#define Bb   4
#define Ss   2048
#define HIDD 1024
#define Hh   16
#define Dd   64
#define M_TOT (Bb*Ss)   // 8192

// ---------------- scratch (static device globals; allocation-free) ----------
__device__ float g_V[(size_t)M_TOT*HIDD];
__device__ __nv_bfloat16 g_Ahi[(size_t)M_TOT*HIDD];
__device__ __nv_bfloat16 g_Alo[(size_t)M_TOT*HIDD];
__device__ __nv_bfloat16 g_Whi[(size_t)HIDD*HIDD];
__device__ __nv_bfloat16 g_Wlo[(size_t)HIDD*HIDD];
__device__ __nv_bfloat16 g_Qhi[(size_t)M_TOT*HIDD];
__device__ __nv_bfloat16 g_Qlo[(size_t)M_TOT*HIDD];
__device__ __nv_bfloat16 g_Khi[(size_t)M_TOT*HIDD];
__device__ __nv_bfloat16 g_Klo[(size_t)M_TOT*HIDD];
__device__ __nv_bfloat16 g_Vthi[(size_t)M_TOT*HIDD];  // [b][h][d][s]
__device__ __nv_bfloat16 g_Vtlo[(size_t)M_TOT*HIDD];

// ---------------- helpers ----------------------------------------------------
__device__ __forceinline__ uint32_t smem_u32(const void* p) {
    return (uint32_t)__cvta_generic_to_shared(p);
}
#define CP16(dst,src)  asm volatile("cp.async.cg.shared.global [%0], [%1], 16;" :: "r"(dst), "l"(src) : "memory")
#define CP_COMMIT()    asm volatile("cp.async.commit_group;" ::: "memory")
#define CP_WAIT0()     asm volatile("cp.async.wait_group 0;" ::: "memory")

#define LDSM4(r0,r1,r2,r3,a) \
    asm volatile("ldmatrix.sync.aligned.m8n8.x4.shared.b16 {%0,%1,%2,%3}, [%4];" \
                 : "=r"(r0), "=r"(r1), "=r"(r2), "=r"(r3) : "r"(a))

#define MMA16816(d,a,b) \
    asm volatile("mma.sync.aligned.m16n8k16.row.col.f32.bf16.bf16.f32 " \
                 "{%0,%1,%2,%3}, {%4,%5,%6,%7}, {%8,%9}, {%0,%1,%2,%3};" \
                 : "+f"((d)[0]), "+f"((d)[1]), "+f"((d)[2]), "+f"((d)[3]) \
                 : "r"((a)[0]), "r"((a)[1]), "r"((a)[2]), "r"((a)[3]), \
                   "r"((b)[0]), "r"((b)[1]))

__device__ __forceinline__ uint32_t pack_bf2(__nv_bfloat16 a, __nv_bfloat16 b) {
    __nv_bfloat162 t = __halves2bfloat162(a, b);
    return *reinterpret_cast<uint32_t*>(&t);
}
// split two floats into packed hi and packed lo bf16x2
__device__ __forceinline__ void split2(float x, float y, uint32_t& hi, uint32_t& lo) {
    __nv_bfloat16 hx = __float2bfloat16(x), hy = __float2bfloat16(y);
    __nv_bfloat16 lx = __float2bfloat16(x - __bfloat162float(hx));
    __nv_bfloat16 ly = __float2bfloat16(y - __bfloat162float(hy));
    hi = pack_bf2(hx, hy);
    lo = pack_bf2(lx, ly);
}

// ---------------- conversion kernels ----------------------------------------
__global__ __launch_bounds__(256) void cvt_act(const float4* __restrict__ x,
                                               __nv_bfloat162* __restrict__ hi,
                                               __nv_bfloat162* __restrict__ lo, int n4) {
    int i = blockIdx.x * blockDim.x + threadIdx.x;
    if (i >= n4) return;
    float4 v = x[i];
    uint32_t h0, l0, h1, l1;
    split2(v.x, v.y, h0, l0);
    split2(v.z, v.w, h1, l1);
    hi[2*i]   = *reinterpret_cast<__nv_bfloat162*>(&h0);
    hi[2*i+1] = *reinterpret_cast<__nv_bfloat162*>(&h1);
    lo[2*i]   = *reinterpret_cast<__nv_bfloat162*>(&l0);
    lo[2*i+1] = *reinterpret_cast<__nv_bfloat162*>(&l1);
}

// W [K,N] fp32 -> hi/lo [N,K] bf16 (transpose)
__global__ __launch_bounds__(256) void cvt_wT(const float* __restrict__ W,
                                              __nv_bfloat16* __restrict__ hi,
                                              __nv_bfloat16* __restrict__ lo) {
    __shared__ float t[32][33];
    int n0 = blockIdx.x * 32, k0 = blockIdx.y * 32;
    int tx = threadIdx.x, ty = threadIdx.y;   // 32 x 8
    #pragma unroll
    for (int i = 0; i < 32; i += 8)
        t[ty + i][tx] = W[(size_t)(k0 + ty + i) * HIDD + n0 + tx];
    __syncthreads();
    #pragma unroll
    for (int i = 0; i < 32; i += 8) {
        float v = t[tx][ty + i];
        __nv_bfloat16 h = __float2bfloat16(v);
        __nv_bfloat16 l = __float2bfloat16(v - __bfloat162float(h));
        size_t o = (size_t)(n0 + ty + i) * HIDD + k0 + tx;
        hi[o] = h; lo[o] = l;
    }
}

// V fp32 [b*S+s][h*64+d] -> Vt hi/lo [(b*16+h)*64+d][s]
__global__ __launch_bounds__(256) void cvt_vT(const float* __restrict__ V,
                                              __nv_bfloat16* __restrict__ hi,
                                              __nv_bfloat16* __restrict__ lo) {
    __shared__ float t[32][33];
    int s0 = blockIdx.x * 32, d0 = blockIdx.y * 32;
    int bh = blockIdx.z;                      // b*16+h
    int b = bh >> 4, h = bh & 15;
    int tx = threadIdx.x, ty = threadIdx.y;   // 32 x 8
    #pragma unroll
    for (int i = 0; i < 32; i += 8)
        t[ty + i][tx] = V[(size_t)(b*Ss + s0 + ty + i) * HIDD + h*Dd + d0 + tx]; // t[s][d]
    __syncthreads();
    #pragma unroll
    for (int i = 0; i < 32; i += 8) {
        float v = t[tx][ty + i];              // s = s0+tx, d = d0+ty+i
        __nv_bfloat16 hb = __float2bfloat16(v);
        __nv_bfloat16 lb = __float2bfloat16(v - __bfloat162float(hb));
        size_t o = ((size_t)bh * Dd + d0 + ty + i) * Ss + s0 + tx;
        hi[o] = hb; lo[o] = lb;
    }
}

// ---------------- mma.sync bf16x3 GEMM ---------------------------------------
#define KTOT 1024
#define GBK  32
#define NSTG (KTOT/GBK)
#define BSTR 40
#define TILE_B (128*BSTR*2)
#define STG_B  (4*TILE_B)
#define GEMM_SMEM (2*STG_B)

template<bool SPLIT>
__global__ __launch_bounds__(256) void gemm_kernel(
    const __nv_bfloat16* __restrict__ Ahi, const __nv_bfloat16* __restrict__ Alo,
    const __nv_bfloat16* __restrict__ Bhi, const __nv_bfloat16* __restrict__ Blo,
    float* __restrict__ C,
    __nv_bfloat16* __restrict__ Chi, __nv_bfloat16* __restrict__ Clo)
{
    extern __shared__ char smraw[];
    const uint32_t sb = smem_u32(smraw);
    const int tid = threadIdx.x;
    const int wid = tid >> 5, lane = tid & 31;
    const int m0 = blockIdx.y * 128;
    const int n0 = blockIdx.x * 128;
    const int wm = (wid & 3) * 32;
    const int wn = (wid >> 2) * 64;

    const char* gA_hi = (const char*)(Ahi + (size_t)m0 * KTOT);
    const char* gA_lo = (const char*)(Alo + (size_t)m0 * KTOT);
    const char* gB_hi = (const char*)(Bhi + (size_t)n0 * KTOT);
    const char* gB_lo = (const char*)(Blo + (size_t)n0 * KTOT);

    auto load_stage = [&](int it, int s) {
        const uint32_t stg = sb + (uint32_t)s * STG_B;
        const size_t kb = (size_t)it * GBK * 2;
        const char* srcs[4] = { gA_hi + kb, gA_lo + kb, gB_hi + kb, gB_lo + kb };
        #pragma unroll
        for (int op = 0; op < 4; op++) {
            const char* g = srcs[op];
            const uint32_t tb = stg + (uint32_t)op * TILE_B;
            #pragma unroll
            for (int j = 0; j < 2; j++) {
                int chunk = j * 256 + tid;
                int r = chunk >> 2, c = chunk & 3;
                CP16(tb + (uint32_t)(r * 80 + c * 16),
                     g + (size_t)r * (KTOT * 2) + c * 16);
            }
        }
        CP_COMMIT();
    };

    const uint32_t a_off = (uint32_t)((lane & 15) * 80 + (lane >> 4) * 16);
    const uint32_t b_off = (uint32_t)((((lane >> 4) & 1) * 8 + (lane & 7)) * 80 +
                                      ((lane >> 3) & 1) * 16);

    float acc[2][8][4];
    #pragma unroll
    for (int mi = 0; mi < 2; mi++)
        #pragma unroll
        for (int ni = 0; ni < 8; ni++)
            #pragma unroll
            for (int r = 0; r < 4; r++) acc[mi][ni][r] = 0.0f;

    load_stage(0, 0);

    #pragma unroll 1
    for (int it = 0; it < NSTG; it++) {
        const int s = it & 1;
        CP_WAIT0();
        __syncthreads();
        if (it + 1 < NSTG) load_stage(it + 1, 1 - s);

        const uint32_t stg = sb + (uint32_t)s * STG_B;
        const uint32_t tAhi = stg;
        const uint32_t tAlo = stg + TILE_B;
        const uint32_t tBhi = stg + 2 * TILE_B;
        const uint32_t tBlo = stg + 3 * TILE_B;

        #pragma unroll
        for (int kk = 0; kk < 2; kk++) {
            const uint32_t koff = (uint32_t)kk * 32;
            uint32_t ah[2][4], al[2][4];
            #pragma unroll
            for (int mi = 0; mi < 2; mi++) {
                uint32_t ra = (uint32_t)((wm + mi * 16) * 80) + a_off + koff;
                LDSM4(ah[mi][0], ah[mi][1], ah[mi][2], ah[mi][3], tAhi + ra);
                LDSM4(al[mi][0], al[mi][1], al[mi][2], al[mi][3], tAlo + ra);
            }
            uint32_t bh[8][2];
            #pragma unroll
            for (int j = 0; j < 4; j++) {
                uint32_t rb = (uint32_t)((wn + j * 16) * 80) + b_off + koff;
                LDSM4(bh[2*j][0], bh[2*j][1], bh[2*j+1][0], bh[2*j+1][1], tBhi + rb);
            }
            #pragma unroll
            for (int mi = 0; mi < 2; mi++)
                #pragma unroll
                for (int ni = 0; ni < 8; ni++) MMA16816(acc[mi][ni], ah[mi], bh[ni]);
            #pragma unroll
            for (int mi = 0; mi < 2; mi++)
                #pragma unroll
                for (int ni = 0; ni < 8; ni++) MMA16816(acc[mi][ni], al[mi], bh[ni]);
            #pragma unroll
            for (int j = 0; j < 4; j++) {
                uint32_t rb = (uint32_t)((wn + j * 16) * 80) + b_off + koff;
                LDSM4(bh[2*j][0], bh[2*j][1], bh[2*j+1][0], bh[2*j+1][1], tBlo + rb);
            }
            #pragma unroll
            for (int mi = 0; mi < 2; mi++)
                #pragma unroll
                for (int ni = 0; ni < 8; ni++) MMA16816(acc[mi][ni], ah[mi], bh[ni]);
        }
        __syncthreads();
    }

    const int r_in = lane >> 2;
    const int c_in = (lane & 3) * 2;
    #pragma unroll
    for (int mi = 0; mi < 2; mi++) {
        #pragma unroll
        for (int ni = 0; ni < 8; ni++) {
            size_t o0 = (size_t)(m0 + wm + mi * 16 + r_in) * HIDD + n0 + wn + ni * 8 + c_in;
            size_t o1 = o0 + 8 * HIDD;
            if (SPLIT) {
                uint32_t h, l;
                split2(acc[mi][ni][0], acc[mi][ni][1], h, l);
                *(uint32_t*)(Chi + o0) = h; *(uint32_t*)(Clo + o0) = l;
                split2(acc[mi][ni][2], acc[mi][ni][3], h, l);
                *(uint32_t*)(Chi + o1) = h; *(uint32_t*)(Clo + o1) = l;
            } else {
                *(float2*)(C + o0) = make_float2(acc[mi][ni][0], acc[mi][ni][1]);
                *(float2*)(C + o1) = make_float2(acc[mi][ni][2], acc[mi][ni][3]);
            }
        }
    }
}

// ---------------- tensor-core flash attention (bf16x3) -----------------------
// CTA: 128 queries x one (b,h). 8 warps x 16 rows. Key tiles of 64, 32 iters.
#define ABQ 128
#define ABK 64
#define ASTR 144                    // smem row stride bytes (72 bf16)
#define SQH 0
#define SQL (128*ASTR)              // 18432
#define SQTOT (2*128*ASTR)          // 36864
#define AOFF_KH 0
#define AOFF_KL (64*ASTR)           // 9216
#define AOFF_VH (2*64*ASTR)
#define AOFF_VL (3*64*ASTR)
#define ASTG_B (4*64*ASTR)          // 36864
#define ATT_SMEM (SQTOT + 2*ASTG_B) // 110592

__global__ __launch_bounds__(256) void attn_kernel(
    const __nv_bfloat16* __restrict__ Qhi, const __nv_bfloat16* __restrict__ Qlo,
    const __nv_bfloat16* __restrict__ Khi, const __nv_bfloat16* __restrict__ Klo,
    const __nv_bfloat16* __restrict__ Vthi, const __nv_bfloat16* __restrict__ Vtlo,
    __nv_bfloat16* __restrict__ Ohi, __nv_bfloat16* __restrict__ Olo)
{
    extern __shared__ char smraw[];
    const uint32_t sb = smem_u32(smraw);
    const int tid = threadIdx.x;
    const int wid = tid >> 5, lane = tid & 31;
    const int q0 = blockIdx.x * ABQ;
    const int h  = blockIdx.y;
    const int b  = blockIdx.z;
    const int wm = wid * 16;

    const char* qh_base = (const char*)(Qhi + (size_t)(b*Ss + q0)*HIDD + h*Dd);
    const char* ql_base = (const char*)(Qlo + (size_t)(b*Ss + q0)*HIDD + h*Dd);
    const char* kh_base = (const char*)(Khi + (size_t)(b*Ss)*HIDD + h*Dd);
    const char* kl_base = (const char*)(Klo + (size_t)(b*Ss)*HIDD + h*Dd);
    const char* vh_base = (const char*)(Vthi + ((size_t)(b*Hh + h)*Dd)*Ss);
    const char* vl_base = (const char*)(Vtlo + ((size_t)(b*Hh + h)*Dd)*Ss);

    // ---- Q staging loads ----
    #pragma unroll
    for (int j = 0; j < 4; j++) {
        int idx = j * 256 + tid;           // 0..1023
        int r = idx >> 3, c = idx & 7;
        CP16(sb + SQH + (uint32_t)(r*ASTR + c*16), qh_base + (size_t)r*2048 + c*16);
        CP16(sb + SQL + (uint32_t)(r*ASTR + c*16), ql_base + (size_t)r*2048 + c*16);
    }
    auto load_stage = [&](int kt, int s) {
        const uint32_t stg = sb + SQTOT + (uint32_t)s * ASTG_B;
        const size_t krow = (size_t)kt * ABK;
        #pragma unroll
        for (int j = 0; j < 2; j++) {
            int idx = j * 256 + tid;       // 0..511
            int r = idx >> 3, c = idx & 7;
            uint32_t so = (uint32_t)(r*ASTR + c*16);
            CP16(stg + AOFF_KH + so, kh_base + (krow + r)*2048 + c*16);
            CP16(stg + AOFF_KL + so, kl_base + (krow + r)*2048 + c*16);
            CP16(stg + AOFF_VH + so, vh_base + (size_t)r*4096 + krow*2 + c*16);
            CP16(stg + AOFF_VL + so, vl_base + (size_t)r*4096 + krow*2 + c*16);
        }
    };
    load_stage(0, 0);
    CP_COMMIT();

    const uint32_t a_off = (uint32_t)((lane & 15) * ASTR + (lane >> 4) * 16);
    const uint32_t b_off = (uint32_t)((((lane >> 4) & 1) * 8 + (lane & 7)) * ASTR +
                                      ((lane >> 3) & 1) * 16);

    uint32_t ah[4][4], al[4][4];          // Q fragments, held all kernel
    float oacc[8][4];
    #pragma unroll
    for (int j = 0; j < 8; j++)
        #pragma unroll
        for (int r = 0; r < 4; r++) oacc[j][r] = 0.0f;
    float m0 = -1e30f, m1 = -1e30f, l0 = 0.0f, l1 = 0.0f;
    const float csc = 0.125f * 1.44269504088896340736f;

    #pragma unroll 1
    for (int it = 0; it < Ss/ABK; it++) {
        const int s = it & 1;
        CP_WAIT0();
        __syncthreads();
        if (it == 0) {
            #pragma unroll
            for (int kk = 0; kk < 4; kk++) {
                uint32_t ra = (uint32_t)(wm * ASTR) + a_off + kk * 32;
                LDSM4(ah[kk][0], ah[kk][1], ah[kk][2], ah[kk][3], sb + SQH + ra);
                LDSM4(al[kk][0], al[kk][1], al[kk][2], al[kk][3], sb + SQL + ra);
            }
        }
        if (it + 1 < Ss/ABK) { load_stage(it + 1, 1 - s); CP_COMMIT(); }

        const uint32_t stg = sb + SQTOT + (uint32_t)s * ASTG_B;

        // ---- S = Q K^T (bf16x3) ----
        float sacc[8][4];
        #pragma unroll
        for (int j = 0; j < 8; j++)
            #pragma unroll
            for (int r = 0; r < 4; r++) sacc[j][r] = 0.0f;
        #pragma unroll
        for (int kk = 0; kk < 4; kk++) {
            uint32_t bh[8][2], bl[8][2];
            #pragma unroll
            for (int j = 0; j < 4; j++) {
                uint32_t rb = (uint32_t)(j * 16 * ASTR) + b_off + kk * 32;
                LDSM4(bh[2*j][0], bh[2*j][1], bh[2*j+1][0], bh[2*j+1][1], stg + AOFF_KH + rb);
                LDSM4(bl[2*j][0], bl[2*j][1], bl[2*j+1][0], bl[2*j+1][1], stg + AOFF_KL + rb);
            }
            #pragma unroll
            for (int j = 0; j < 8; j++) MMA16816(sacc[j], ah[kk], bh[j]);
            #pragma unroll
            for (int j = 0; j < 8; j++) MMA16816(sacc[j], al[kk], bh[j]);
            #pragma unroll
            for (int j = 0; j < 8; j++) MMA16816(sacc[j], ah[kk], bl[j]);
        }

        // ---- online softmax (base-2, t = S*csc) ----
        float mx0 = -1e30f, mx1 = -1e30f;
        #pragma unroll
        for (int j = 0; j < 8; j++) {
            mx0 = fmaxf(mx0, fmaxf(sacc[j][0], sacc[j][1]));
            mx1 = fmaxf(mx1, fmaxf(sacc[j][2], sacc[j][3]));
        }
        mx0 = fmaxf(mx0, __shfl_xor_sync(0xffffffffu, mx0, 1));
        mx0 = fmaxf(mx0, __shfl_xor_sync(0xffffffffu, mx0, 2));
        mx1 = fmaxf(mx1, __shfl_xor_sync(0xffffffffu, mx1, 1));
        mx1 = fmaxf(mx1, __shfl_xor_sync(0xffffffffu, mx1, 2));
        mx0 *= csc; mx1 *= csc;
        float nm0 = fmaxf(m0, mx0), nm1 = fmaxf(m1, mx1);
        float a0 = exp2f(m0 - nm0), a1 = exp2f(m1 - nm1);
        m0 = nm0; m1 = nm1;

        float sum0 = 0.0f, sum1 = 0.0f;
        #pragma unroll
        for (int j = 0; j < 8; j++) {
            sacc[j][0] = exp2f(fmaf(sacc[j][0], csc, -nm0));
            sacc[j][1] = exp2f(fmaf(sacc[j][1], csc, -nm0));
            sacc[j][2] = exp2f(fmaf(sacc[j][2], csc, -nm1));
            sacc[j][3] = exp2f(fmaf(sacc[j][3], csc, -nm1));
            sum0 += sacc[j][0] + sacc[j][1];
            sum1 += sacc[j][2] + sacc[j][3];
        }
        sum0 += __shfl_xor_sync(0xffffffffu, sum0, 1);
        sum0 += __shfl_xor_sync(0xffffffffu, sum0, 2);
        sum1 += __shfl_xor_sync(0xffffffffu, sum1, 1);
        sum1 += __shfl_xor_sync(0xffffffffu, sum1, 2);
        l0 = l0 * a0 + sum0;
        l1 = l1 * a1 + sum1;
        #pragma unroll
        for (int j = 0; j < 8; j++) {
            oacc[j][0] *= a0; oacc[j][1] *= a0;
            oacc[j][2] *= a1; oacc[j][3] *= a1;
        }

        // ---- O += P V (bf16x3); P frags from sacc via C->A identity ----
        #pragma unroll
        for (int kk = 0; kk < 4; kk++) {
            uint32_t pah[4], pal[4];
            split2(sacc[2*kk][0],   sacc[2*kk][1],   pah[0], pal[0]);
            split2(sacc[2*kk][2],   sacc[2*kk][3],   pah[1], pal[1]);
            split2(sacc[2*kk+1][0], sacc[2*kk+1][1], pah[2], pal[2]);
            split2(sacc[2*kk+1][2], sacc[2*kk+1][3], pah[3], pal[3]);

            uint32_t bh[8][2], bl[8][2];
            #pragma unroll
            for (int j = 0; j < 4; j++) {
                uint32_t rb = (uint32_t)(j * 16 * ASTR) + b_off + kk * 32;
                LDSM4(bh[2*j][0], bh[2*j][1], bh[2*j+1][0], bh[2*j+1][1], stg + AOFF_VH + rb);
                LDSM4(bl[2*j][0], bl[2*j][1], bl[2*j+1][0], bl[2*j+1][1], stg + AOFF_VL + rb);
            }
            #pragma unroll
            for (int j = 0; j < 8; j++) MMA16816(oacc[j], pah, bh[j]);
            #pragma unroll
            for (int j = 0; j < 8; j++) MMA16816(oacc[j], pal, bh[j]);
            #pragma unroll
            for (int j = 0; j < 8; j++) MMA16816(oacc[j], pah, bl[j]);
        }
        __syncthreads();
    }

    // ---- epilogue: normalize + split-write into final GEMM's A buffers ----
    const float inv0 = 1.0f / l0, inv1 = 1.0f / l1;
    const int r0 = lane >> 2;
    const size_t row0 = (size_t)(b*Ss + q0 + wm + r0) * HIDD + h*Dd + (lane & 3) * 2;
    const size_t row1 = row0 + 8 * HIDD;
    #pragma unroll
    for (int j = 0; j < 8; j++) {
        uint32_t hh, ll;
        split2(oacc[j][0] * inv0, oacc[j][1] * inv0, hh, ll);
        *(uint32_t*)(Ohi + row0 + j*8) = hh;
        *(uint32_t*)(Olo + row0 + j*8) = ll;
        split2(oacc[j][2] * inv1, oacc[j][3] * inv1, hh, ll);
        *(uint32_t*)(Ohi + row1 + j*8) = hh;
        *(uint32_t*)(Olo + row1 + j*8) = ll;
    }
}

// ---------------------------------------------------------------------------
extern "C" void kernel_launch(void* const* d_in, const int* in_sizes, int n_in,
                              void* d_out, int out_size)
{
    (void)in_sizes; (void)n_in; (void)out_size;
    const float* q  = (const float*)d_in[0];
    const float* k  = (const float*)d_in[1];
    const float* v  = (const float*)d_in[2];
    const float* Wq = (const float*)d_in[3];
    const float* Wk = (const float*)d_in[4];
    const float* Wv = (const float*)d_in[5];
    const float* Wo = (const float*)d_in[6];
    float* out = (float*)d_out;

    float *pV;
    __nv_bfloat16 *pAhi, *pAlo, *pWhi, *pWlo, *pQhi, *pQlo, *pKhi, *pKlo, *pVthi, *pVtlo;
    cudaGetSymbolAddress((void**)&pV, g_V);
    cudaGetSymbolAddress((void**)&pAhi, g_Ahi);
    cudaGetSymbolAddress((void**)&pAlo, g_Alo);
    cudaGetSymbolAddress((void**)&pWhi, g_Whi);
    cudaGetSymbolAddress((void**)&pWlo, g_Wlo);
    cudaGetSymbolAddress((void**)&pQhi, g_Qhi);
    cudaGetSymbolAddress((void**)&pQlo, g_Qlo);
    cudaGetSymbolAddress((void**)&pKhi, g_Khi);
    cudaGetSymbolAddress((void**)&pKlo, g_Klo);
    cudaGetSymbolAddress((void**)&pVthi, g_Vthi);
    cudaGetSymbolAddress((void**)&pVtlo, g_Vtlo);

    cudaFuncSetAttribute(gemm_kernel<true>,  cudaFuncAttributeMaxDynamicSharedMemorySize, GEMM_SMEM);
    cudaFuncSetAttribute(gemm_kernel<false>, cudaFuncAttributeMaxDynamicSharedMemorySize, GEMM_SMEM);
    cudaFuncSetAttribute(attn_kernel, cudaFuncAttributeMaxDynamicSharedMemorySize, ATT_SMEM);

    const int n4 = (M_TOT * HIDD) / 4;
    const dim3 cvtg(n4 / 256);
    const dim3 wtg(HIDD/32, HIDD/32), wtb(32, 8);
    const dim3 gg(HIDD/128, M_TOT/128);
    const dim3 vtg(Ss/32, Dd/32, Bb*Hh);

    // Q projection -> split
    cvt_act<<<cvtg, 256>>>((const float4*)q, (__nv_bfloat162*)pAhi, (__nv_bfloat162*)pAlo, n4);
    cvt_wT<<<wtg, wtb>>>(Wq, pWhi, pWlo);
    gemm_kernel<true><<<gg, 256, GEMM_SMEM>>>(pAhi, pAlo, pWhi, pWlo, nullptr, pQhi, pQlo);
    // K projection -> split
    cvt_act<<<cvtg, 256>>>((const float4*)k, (__nv_bfloat162*)pAhi, (__nv_bfloat162*)pAlo, n4);
    cvt_wT<<<wtg, wtb>>>(Wk, pWhi, pWlo);
    gemm_kernel<true><<<gg, 256, GEMM_SMEM>>>(pAhi, pAlo, pWhi, pWlo, nullptr, pKhi, pKlo);
    // V projection -> fp32, then transposed split
    cvt_act<<<cvtg, 256>>>((const float4*)v, (__nv_bfloat162*)pAhi, (__nv_bfloat162*)pAlo, n4);
    cvt_wT<<<wtg, wtb>>>(Wv, pWhi, pWlo);
    gemm_kernel<false><<<gg, 256, GEMM_SMEM>>>(pAhi, pAlo, pWhi, pWlo, pV, nullptr, nullptr);
    cvt_vT<<<vtg, wtb>>>(pV, pVthi, pVtlo);

    // attention (writes split O into pAhi/pAlo for the final GEMM)
    attn_kernel<<<dim3(Ss/ABQ, Hh, Bb), 256, ATT_SMEM>>>(
        pQhi, pQlo, pKhi, pKlo, pVthi, pVtlo, pAhi, pAlo);

    // output projection
    cvt_wT<<<wtg, wtb>>>(Wo, pWhi, pWlo);
    gemm_kernel<false><<<gg, 256, GEMM_SMEM>>>(pAhi, pAlo, pWhi, pWlo, out, nullptr, nullptr);
}

// round 5
// speedup vs baseline: 3.2140x; 1.1323x over previous
#include <cuda_runtime.h>
#include <cuda_bf16.h>
#include <cstdint>

#define Bb   4
#define Ss   2048
#define HIDD 1024
#define Hh   16
#define Dd   64
#define M_TOT (Bb*Ss)   // 8192

// ---------------- scratch (static device globals; allocation-free) ----------
__device__ float g_V[(size_t)M_TOT*HIDD];
__device__ __nv_bfloat16 g_Aq_hi[(size_t)M_TOT*HIDD];   // q split; later attn-out split
__device__ __nv_bfloat16 g_Aq_lo[(size_t)M_TOT*HIDD];
__device__ __nv_bfloat16 g_Ak_hi[(size_t)M_TOT*HIDD];
__device__ __nv_bfloat16 g_Ak_lo[(size_t)M_TOT*HIDD];
__device__ __nv_bfloat16 g_Av_hi[(size_t)M_TOT*HIDD];
__device__ __nv_bfloat16 g_Av_lo[(size_t)M_TOT*HIDD];
__device__ __nv_bfloat16 g_Whi[(size_t)4*HIDD*HIDD];    // [z][N][K], z: q,k,v,o
__device__ __nv_bfloat16 g_Wlo[(size_t)4*HIDD*HIDD];
__device__ __nv_bfloat16 g_Qhi[(size_t)M_TOT*HIDD];
__device__ __nv_bfloat16 g_Qlo[(size_t)M_TOT*HIDD];
__device__ __nv_bfloat16 g_Khi[(size_t)M_TOT*HIDD];
__device__ __nv_bfloat16 g_Klo[(size_t)M_TOT*HIDD];
__device__ __nv_bfloat16 g_Vthi[(size_t)M_TOT*HIDD];    // [b][h][d][s]
__device__ __nv_bfloat16 g_Vtlo[(size_t)M_TOT*HIDD];

// ---------------- helpers ----------------------------------------------------
__device__ __forceinline__ uint32_t smem_u32(const void* p) {
    return (uint32_t)__cvta_generic_to_shared(p);
}
#define CP16(dst,src)  asm volatile("cp.async.cg.shared.global [%0], [%1], 16;" :: "r"(dst), "l"(src) : "memory")
#define CP_COMMIT()    asm volatile("cp.async.commit_group;" ::: "memory")
#define CP_WAIT0()     asm volatile("cp.async.wait_group 0;" ::: "memory")

#define LDSM4(r0,r1,r2,r3,a) \
    asm volatile("ldmatrix.sync.aligned.m8n8.x4.shared.b16 {%0,%1,%2,%3}, [%4];" \
                 : "=r"(r0), "=r"(r1), "=r"(r2), "=r"(r3) : "r"(a))

#define MMA16816(d,a,b) \
    asm volatile("mma.sync.aligned.m16n8k16.row.col.f32.bf16.bf16.f32 " \
                 "{%0,%1,%2,%3}, {%4,%5,%6,%7}, {%8,%9}, {%0,%1,%2,%3};" \
                 : "+f"((d)[0]), "+f"((d)[1]), "+f"((d)[2]), "+f"((d)[3]) \
                 : "r"((a)[0]), "r"((a)[1]), "r"((a)[2]), "r"((a)[3]), \
                   "r"((b)[0]), "r"((b)[1]))

__device__ __forceinline__ uint32_t pack_bf2(__nv_bfloat16 a, __nv_bfloat16 b) {
    __nv_bfloat162 t = __halves2bfloat162(a, b);
    return *reinterpret_cast<uint32_t*>(&t);
}
__device__ __forceinline__ void split2(float x, float y, uint32_t& hi, uint32_t& lo) {
    __nv_bfloat16 hx = __float2bfloat16(x), hy = __float2bfloat16(y);
    __nv_bfloat16 lx = __float2bfloat16(x - __bfloat162float(hx));
    __nv_bfloat16 ly = __float2bfloat16(y - __bfloat162float(hy));
    hi = pack_bf2(hx, hy);
    lo = pack_bf2(lx, ly);
}

// ---------------- conversion kernels ----------------------------------------
// one launch: splits q,k,v (z = blockIdx.y)
__global__ __launch_bounds__(256) void cvt_act3(
    const float4* __restrict__ q, const float4* __restrict__ k, const float4* __restrict__ v,
    __nv_bfloat162* __restrict__ qh, __nv_bfloat162* __restrict__ ql,
    __nv_bfloat162* __restrict__ kh, __nv_bfloat162* __restrict__ kl,
    __nv_bfloat162* __restrict__ vh, __nv_bfloat162* __restrict__ vl, int n4)
{
    int i = blockIdx.x * blockDim.x + threadIdx.x;
    if (i >= n4) return;
    int z = blockIdx.y;
    const float4* x = (z == 0) ? q : (z == 1) ? k : v;
    __nv_bfloat162* hi = (z == 0) ? qh : (z == 1) ? kh : vh;
    __nv_bfloat162* lo = (z == 0) ? ql : (z == 1) ? kl : vl;
    float4 val = x[i];
    uint32_t h0, l0, h1, l1;
    split2(val.x, val.y, h0, l0);
    split2(val.z, val.w, h1, l1);
    hi[2*i]   = *reinterpret_cast<__nv_bfloat162*>(&h0);
    hi[2*i+1] = *reinterpret_cast<__nv_bfloat162*>(&h1);
    lo[2*i]   = *reinterpret_cast<__nv_bfloat162*>(&l0);
    lo[2*i+1] = *reinterpret_cast<__nv_bfloat162*>(&l1);
}

// one launch: W [K,N] fp32 -> hi/lo [N,K] bf16 for all four weights (z = blockIdx.z)
__global__ __launch_bounds__(256) void cvt_wT4(
    const float* __restrict__ Wq, const float* __restrict__ Wk,
    const float* __restrict__ Wv, const float* __restrict__ Wo,
    __nv_bfloat16* __restrict__ hi, __nv_bfloat16* __restrict__ lo)
{
    __shared__ float t[32][33];
    int z = blockIdx.z;
    const float* W = (z == 0) ? Wq : (z == 1) ? Wk : (z == 2) ? Wv : Wo;
    __nv_bfloat16* hz = hi + (size_t)z * HIDD * HIDD;
    __nv_bfloat16* lz = lo + (size_t)z * HIDD * HIDD;
    int n0 = blockIdx.x * 32, k0 = blockIdx.y * 32;
    int tx = threadIdx.x, ty = threadIdx.y;   // 32 x 8
    #pragma unroll
    for (int i = 0; i < 32; i += 8)
        t[ty + i][tx] = W[(size_t)(k0 + ty + i) * HIDD + n0 + tx];
    __syncthreads();
    #pragma unroll
    for (int i = 0; i < 32; i += 8) {
        float v = t[tx][ty + i];
        __nv_bfloat16 h = __float2bfloat16(v);
        __nv_bfloat16 l = __float2bfloat16(v - __bfloat162float(h));
        size_t o = (size_t)(n0 + ty + i) * HIDD + k0 + tx;
        hz[o] = h; lz[o] = l;
    }
}

// V fp32 [b*S+s][h*64+d] -> Vt hi/lo [(b*16+h)*64+d][s]
__global__ __launch_bounds__(256) void cvt_vT(const float* __restrict__ V,
                                              __nv_bfloat16* __restrict__ hi,
                                              __nv_bfloat16* __restrict__ lo) {
    __shared__ float t[32][33];
    int s0 = blockIdx.x * 32, d0 = blockIdx.y * 32;
    int bh = blockIdx.z;
    int b = bh >> 4, h = bh & 15;
    int tx = threadIdx.x, ty = threadIdx.y;   // 32 x 8
    #pragma unroll
    for (int i = 0; i < 32; i += 8)
        t[ty + i][tx] = V[(size_t)(b*Ss + s0 + ty + i) * HIDD + h*Dd + d0 + tx];
    __syncthreads();
    #pragma unroll
    for (int i = 0; i < 32; i += 8) {
        float v = t[tx][ty + i];
        __nv_bfloat16 hb = __float2bfloat16(v);
        __nv_bfloat16 lb = __float2bfloat16(v - __bfloat162float(hb));
        size_t o = ((size_t)bh * Dd + d0 + ty + i) * Ss + s0 + tx;
        hi[o] = hb; lo[o] = lb;
    }
}

// ---------------- mma.sync bf16x3 GEMM (QKV fused / output proj) -------------
#define KTOT 1024
#define GBK  32
#define NSTG (KTOT/GBK)
#define BSTR 40
#define TILE_B (128*BSTR*2)
#define STG_B  (4*TILE_B)
#define GEMM_SMEM (2*STG_B)

__global__ __launch_bounds__(256) void gemm_all(
    const __nv_bfloat16* __restrict__ Aq_hi, const __nv_bfloat16* __restrict__ Aq_lo,
    const __nv_bfloat16* __restrict__ Ak_hi, const __nv_bfloat16* __restrict__ Ak_lo,
    const __nv_bfloat16* __restrict__ Av_hi, const __nv_bfloat16* __restrict__ Av_lo,
    const __nv_bfloat16* __restrict__ Wh, const __nv_bfloat16* __restrict__ Wl,
    __nv_bfloat16* __restrict__ Qh, __nv_bfloat16* __restrict__ Ql,
    __nv_bfloat16* __restrict__ Kh, __nv_bfloat16* __restrict__ Kl,
    float* __restrict__ Vout, float* __restrict__ Final, int final_pass)
{
    extern __shared__ char smraw[];
    const uint32_t sb = smem_u32(smraw);
    const int tid = threadIdx.x;
    const int wid = tid >> 5, lane = tid & 31;
    const int m0 = blockIdx.y * 128;
    const int n0 = blockIdx.x * 128;
    const int wm = (wid & 3) * 32;
    const int wn = (wid >> 2) * 64;
    const int z  = final_pass ? 3 : (int)blockIdx.z;

    const __nv_bfloat16* Ahi = (z == 1) ? Ak_hi : (z == 2) ? Av_hi : Aq_hi;
    const __nv_bfloat16* Alo = (z == 1) ? Ak_lo : (z == 2) ? Av_lo : Aq_lo;
    const __nv_bfloat16* Bhi = Wh + (size_t)z * HIDD * HIDD;
    const __nv_bfloat16* Blo = Wl + (size_t)z * HIDD * HIDD;

    const char* gA_hi = (const char*)(Ahi + (size_t)m0 * KTOT);
    const char* gA_lo = (const char*)(Alo + (size_t)m0 * KTOT);
    const char* gB_hi = (const char*)(Bhi + (size_t)n0 * KTOT);
    const char* gB_lo = (const char*)(Blo + (size_t)n0 * KTOT);

    auto load_stage = [&](int it, int s) {
        const uint32_t stg = sb + (uint32_t)s * STG_B;
        const size_t kb = (size_t)it * GBK * 2;
        const char* srcs[4] = { gA_hi + kb, gA_lo + kb, gB_hi + kb, gB_lo + kb };
        #pragma unroll
        for (int op = 0; op < 4; op++) {
            const char* g = srcs[op];
            const uint32_t tb = stg + (uint32_t)op * TILE_B;
            #pragma unroll
            for (int j = 0; j < 2; j++) {
                int chunk = j * 256 + tid;
                int r = chunk >> 2, c = chunk & 3;
                CP16(tb + (uint32_t)(r * 80 + c * 16),
                     g + (size_t)r * (KTOT * 2) + c * 16);
            }
        }
        CP_COMMIT();
    };

    const uint32_t a_off = (uint32_t)((lane & 15) * 80 + (lane >> 4) * 16);
    const uint32_t b_off = (uint32_t)((((lane >> 4) & 1) * 8 + (lane & 7)) * 80 +
                                      ((lane >> 3) & 1) * 16);

    float acc[2][8][4];
    #pragma unroll
    for (int mi = 0; mi < 2; mi++)
        #pragma unroll
        for (int ni = 0; ni < 8; ni++)
            #pragma unroll
            for (int r = 0; r < 4; r++) acc[mi][ni][r] = 0.0f;

    load_stage(0, 0);

    #pragma unroll 1
    for (int it = 0; it < NSTG; it++) {
        const int s = it & 1;
        CP_WAIT0();
        __syncthreads();
        if (it + 1 < NSTG) load_stage(it + 1, 1 - s);

        const uint32_t stg = sb + (uint32_t)s * STG_B;
        const uint32_t tAhi = stg;
        const uint32_t tAlo = stg + TILE_B;
        const uint32_t tBhi = stg + 2 * TILE_B;
        const uint32_t tBlo = stg + 3 * TILE_B;

        #pragma unroll
        for (int kk = 0; kk < 2; kk++) {
            const uint32_t koff = (uint32_t)kk * 32;
            uint32_t ah[2][4], al[2][4];
            #pragma unroll
            for (int mi = 0; mi < 2; mi++) {
                uint32_t ra = (uint32_t)((wm + mi * 16) * 80) + a_off + koff;
                LDSM4(ah[mi][0], ah[mi][1], ah[mi][2], ah[mi][3], tAhi + ra);
                LDSM4(al[mi][0], al[mi][1], al[mi][2], al[mi][3], tAlo + ra);
            }
            uint32_t bh[8][2];
            #pragma unroll
            for (int j = 0; j < 4; j++) {
                uint32_t rb = (uint32_t)((wn + j * 16) * 80) + b_off + koff;
                LDSM4(bh[2*j][0], bh[2*j][1], bh[2*j+1][0], bh[2*j+1][1], tBhi + rb);
            }
            #pragma unroll
            for (int mi = 0; mi < 2; mi++)
                #pragma unroll
                for (int ni = 0; ni < 8; ni++) MMA16816(acc[mi][ni], ah[mi], bh[ni]);
            #pragma unroll
            for (int mi = 0; mi < 2; mi++)
                #pragma unroll
                for (int ni = 0; ni < 8; ni++) MMA16816(acc[mi][ni], al[mi], bh[ni]);
            #pragma unroll
            for (int j = 0; j < 4; j++) {
                uint32_t rb = (uint32_t)((wn + j * 16) * 80) + b_off + koff;
                LDSM4(bh[2*j][0], bh[2*j][1], bh[2*j+1][0], bh[2*j+1][1], tBlo + rb);
            }
            #pragma unroll
            for (int mi = 0; mi < 2; mi++)
                #pragma unroll
                for (int ni = 0; ni < 8; ni++) MMA16816(acc[mi][ni], ah[mi], bh[ni]);
        }
        __syncthreads();
    }

    const int r_in = lane >> 2;
    const int c_in = (lane & 3) * 2;
    __nv_bfloat16* Chi = (z == 0) ? Qh : Kh;
    __nv_bfloat16* Clo = (z == 0) ? Ql : Kl;
    float* Cf = (z == 2) ? Vout : Final;
    #pragma unroll
    for (int mi = 0; mi < 2; mi++) {
        #pragma unroll
        for (int ni = 0; ni < 8; ni++) {
            size_t o0 = (size_t)(m0 + wm + mi * 16 + r_in) * HIDD + n0 + wn + ni * 8 + c_in;
            size_t o1 = o0 + 8 * HIDD;
            if (z < 2) {
                uint32_t h, l;
                split2(acc[mi][ni][0], acc[mi][ni][1], h, l);
                *(uint32_t*)(Chi + o0) = h; *(uint32_t*)(Clo + o0) = l;
                split2(acc[mi][ni][2], acc[mi][ni][3], h, l);
                *(uint32_t*)(Chi + o1) = h; *(uint32_t*)(Clo + o1) = l;
            } else {
                *(float2*)(Cf + o0) = make_float2(acc[mi][ni][0], acc[mi][ni][1]);
                *(float2*)(Cf + o1) = make_float2(acc[mi][ni][2], acc[mi][ni][3]);
            }
        }
    }
}

// ---------------- tensor-core flash attention (bf16x3) -----------------------
#define ABQ 128
#define ABK 64
#define ASTR 144
#define SQH 0
#define SQL (128*ASTR)
#define SQTOT (2*128*ASTR)
#define AOFF_KH 0
#define AOFF_KL (64*ASTR)
#define AOFF_VH (2*64*ASTR)
#define AOFF_VL (3*64*ASTR)
#define ASTG_B (4*64*ASTR)
#define ATT_SMEM (SQTOT + 2*ASTG_B)

__global__ __launch_bounds__(256) void attn_kernel(
    const __nv_bfloat16* __restrict__ Qhi, const __nv_bfloat16* __restrict__ Qlo,
    const __nv_bfloat16* __restrict__ Khi, const __nv_bfloat16* __restrict__ Klo,
    const __nv_bfloat16* __restrict__ Vthi, const __nv_bfloat16* __restrict__ Vtlo,
    __nv_bfloat16* __restrict__ Ohi, __nv_bfloat16* __restrict__ Olo)
{
    extern __shared__ char smraw[];
    const uint32_t sb = smem_u32(smraw);
    const int tid = threadIdx.x;
    const int wid = tid >> 5, lane = tid & 31;
    const int q0 = blockIdx.x * ABQ;
    const int h  = blockIdx.y;
    const int b  = blockIdx.z;
    const int wm = wid * 16;

    const char* qh_base = (const char*)(Qhi + (size_t)(b*Ss + q0)*HIDD + h*Dd);
    const char* ql_base = (const char*)(Qlo + (size_t)(b*Ss + q0)*HIDD + h*Dd);
    const char* kh_base = (const char*)(Khi + (size_t)(b*Ss)*HIDD + h*Dd);
    const char* kl_base = (const char*)(Klo + (size_t)(b*Ss)*HIDD + h*Dd);
    const char* vh_base = (const char*)(Vthi + ((size_t)(b*Hh + h)*Dd)*Ss);
    const char* vl_base = (const char*)(Vtlo + ((size_t)(b*Hh + h)*Dd)*Ss);

    #pragma unroll
    for (int j = 0; j < 4; j++) {
        int idx = j * 256 + tid;
        int r = idx >> 3, c = idx & 7;
        CP16(sb + SQH + (uint32_t)(r*ASTR + c*16), qh_base + (size_t)r*2048 + c*16);
        CP16(sb + SQL + (uint32_t)(r*ASTR + c*16), ql_base + (size_t)r*2048 + c*16);
    }
    auto load_stage = [&](int kt, int s) {
        const uint32_t stg = sb + SQTOT + (uint32_t)s * ASTG_B;
        const size_t krow = (size_t)kt * ABK;
        #pragma unroll
        for (int j = 0; j < 2; j++) {
            int idx = j * 256 + tid;
            int r = idx >> 3, c = idx & 7;
            uint32_t so = (uint32_t)(r*ASTR + c*16);
            CP16(stg + AOFF_KH + so, kh_base + (krow + r)*2048 + c*16);
            CP16(stg + AOFF_KL + so, kl_base + (krow + r)*2048 + c*16);
            CP16(stg + AOFF_VH + so, vh_base + (size_t)r*4096 + krow*2 + c*16);
            CP16(stg + AOFF_VL + so, vl_base + (size_t)r*4096 + krow*2 + c*16);
        }
    };
    load_stage(0, 0);
    CP_COMMIT();

    const uint32_t a_off = (uint32_t)((lane & 15) * ASTR + (lane >> 4) * 16);
    const uint32_t b_off = (uint32_t)((((lane >> 4) & 1) * 8 + (lane & 7)) * ASTR +
                                      ((lane >> 3) & 1) * 16);

    uint32_t ah[4][4], al[4][4];
    float oacc[8][4];
    #pragma unroll
    for (int j = 0; j < 8; j++)
        #pragma unroll
        for (int r = 0; r < 4; r++) oacc[j][r] = 0.0f;
    float m0 = -1e30f, m1 = -1e30f, l0 = 0.0f, l1 = 0.0f;
    const float csc = 0.125f * 1.44269504088896340736f;

    #pragma unroll 1
    for (int it = 0; it < Ss/ABK; it++) {
        const int s = it & 1;
        CP_WAIT0();
        __syncthreads();
        if (it == 0) {
            #pragma unroll
            for (int kk = 0; kk < 4; kk++) {
                uint32_t ra = (uint32_t)(wm * ASTR) + a_off + kk * 32;
                LDSM4(ah[kk][0], ah[kk][1], ah[kk][2], ah[kk][3], sb + SQH + ra);
                LDSM4(al[kk][0], al[kk][1], al[kk][2], al[kk][3], sb + SQL + ra);
            }
        }
        if (it + 1 < Ss/ABK) { load_stage(it + 1, 1 - s); CP_COMMIT(); }

        const uint32_t stg = sb + SQTOT + (uint32_t)s * ASTG_B;

        float sacc[8][4];
        #pragma unroll
        for (int j = 0; j < 8; j++)
            #pragma unroll
            for (int r = 0; r < 4; r++) sacc[j][r] = 0.0f;
        #pragma unroll
        for (int kk = 0; kk < 4; kk++) {
            uint32_t bh[8][2], bl[8][2];
            #pragma unroll
            for (int j = 0; j < 4; j++) {
                uint32_t rb = (uint32_t)(j * 16 * ASTR) + b_off + kk * 32;
                LDSM4(bh[2*j][0], bh[2*j][1], bh[2*j+1][0], bh[2*j+1][1], stg + AOFF_KH + rb);
                LDSM4(bl[2*j][0], bl[2*j][1], bl[2*j+1][0], bl[2*j+1][1], stg + AOFF_KL + rb);
            }
            #pragma unroll
            for (int j = 0; j < 8; j++) MMA16816(sacc[j], ah[kk], bh[j]);
            #pragma unroll
            for (int j = 0; j < 8; j++) MMA16816(sacc[j], al[kk], bh[j]);
            #pragma unroll
            for (int j = 0; j < 8; j++) MMA16816(sacc[j], ah[kk], bl[j]);
        }

        float mx0 = -1e30f, mx1 = -1e30f;
        #pragma unroll
        for (int j = 0; j < 8; j++) {
            mx0 = fmaxf(mx0, fmaxf(sacc[j][0], sacc[j][1]));
            mx1 = fmaxf(mx1, fmaxf(sacc[j][2], sacc[j][3]));
        }
        mx0 = fmaxf(mx0, __shfl_xor_sync(0xffffffffu, mx0, 1));
        mx0 = fmaxf(mx0, __shfl_xor_sync(0xffffffffu, mx0, 2));
        mx1 = fmaxf(mx1, __shfl_xor_sync(0xffffffffu, mx1, 1));
        mx1 = fmaxf(mx1, __shfl_xor_sync(0xffffffffu, mx1, 2));
        mx0 *= csc; mx1 *= csc;
        float nm0 = fmaxf(m0, mx0), nm1 = fmaxf(m1, mx1);
        float a0 = exp2f(m0 - nm0), a1 = exp2f(m1 - nm1);
        m0 = nm0; m1 = nm1;

        float sum0 = 0.0f, sum1 = 0.0f;
        #pragma unroll
        for (int j = 0; j < 8; j++) {
            sacc[j][0] = exp2f(fmaf(sacc[j][0], csc, -nm0));
            sacc[j][1] = exp2f(fmaf(sacc[j][1], csc, -nm0));
            sacc[j][2] = exp2f(fmaf(sacc[j][2], csc, -nm1));
            sacc[j][3] = exp2f(fmaf(sacc[j][3], csc, -nm1));
            sum0 += sacc[j][0] + sacc[j][1];
            sum1 += sacc[j][2] + sacc[j][3];
        }
        sum0 += __shfl_xor_sync(0xffffffffu, sum0, 1);
        sum0 += __shfl_xor_sync(0xffffffffu, sum0, 2);
        sum1 += __shfl_xor_sync(0xffffffffu, sum1, 1);
        sum1 += __shfl_xor_sync(0xffffffffu, sum1, 2);
        l0 = l0 * a0 + sum0;
        l1 = l1 * a1 + sum1;
        #pragma unroll
        for (int j = 0; j < 8; j++) {
            oacc[j][0] *= a0; oacc[j][1] *= a0;
            oacc[j][2] *= a1; oacc[j][3] *= a1;
        }

        #pragma unroll
        for (int kk = 0; kk < 4; kk++) {
            uint32_t pah[4], pal[4];
            split2(sacc[2*kk][0],   sacc[2*kk][1],   pah[0], pal[0]);
            split2(sacc[2*kk][2],   sacc[2*kk][3],   pah[1], pal[1]);
            split2(sacc[2*kk+1][0], sacc[2*kk+1][1], pah[2], pal[2]);
            split2(sacc[2*kk+1][2], sacc[2*kk+1][3], pah[3], pal[3]);

            uint32_t bh[8][2], bl[8][2];
            #pragma unroll
            for (int j = 0; j < 4; j++) {
                uint32_t rb = (uint32_t)(j * 16 * ASTR) + b_off + kk * 32;
                LDSM4(bh[2*j][0], bh[2*j][1], bh[2*j+1][0], bh[2*j+1][1], stg + AOFF_VH + rb);
                LDSM4(bl[2*j][0], bl[2*j][1], bl[2*j+1][0], bl[2*j+1][1], stg + AOFF_VL + rb);
            }
            #pragma unroll
            for (int j = 0; j < 8; j++) MMA16816(oacc[j], pah, bh[j]);
            #pragma unroll
            for (int j = 0; j < 8; j++) MMA16816(oacc[j], pal, bh[j]);
            #pragma unroll
            for (int j = 0; j < 8; j++) MMA16816(oacc[j], pah, bl[j]);
        }
        __syncthreads();
    }

    const float inv0 = 1.0f / l0, inv1 = 1.0f / l1;
    const int r0 = lane >> 2;
    const size_t row0 = (size_t)(b*Ss + q0 + wm + r0) * HIDD + h*Dd + (lane & 3) * 2;
    const size_t row1 = row0 + 8 * HIDD;
    #pragma unroll
    for (int j = 0; j < 8; j++) {
        uint32_t hh, ll;
        split2(oacc[j][0] * inv0, oacc[j][1] * inv0, hh, ll);
        *(uint32_t*)(Ohi + row0 + j*8) = hh;
        *(uint32_t*)(Olo + row0 + j*8) = ll;
        split2(oacc[j][2] * inv1, oacc[j][3] * inv1, hh, ll);
        *(uint32_t*)(Ohi + row1 + j*8) = hh;
        *(uint32_t*)(Olo + row1 + j*8) = ll;
    }
}

// ---------------------------------------------------------------------------
extern "C" void kernel_launch(void* const* d_in, const int* in_sizes, int n_in,
                              void* d_out, int out_size)
{
    (void)in_sizes; (void)n_in; (void)out_size;
    const float* q  = (const float*)d_in[0];
    const float* k  = (const float*)d_in[1];
    const float* v  = (const float*)d_in[2];
    const float* Wq = (const float*)d_in[3];
    const float* Wk = (const float*)d_in[4];
    const float* Wv = (const float*)d_in[5];
    const float* Wo = (const float*)d_in[6];
    float* out = (float*)d_out;

    float *pV;
    __nv_bfloat16 *pAqh, *pAql, *pAkh, *pAkl, *pAvh, *pAvl;
    __nv_bfloat16 *pWhi, *pWlo, *pQhi, *pQlo, *pKhi, *pKlo, *pVthi, *pVtlo;
    cudaGetSymbolAddress((void**)&pV, g_V);
    cudaGetSymbolAddress((void**)&pAqh, g_Aq_hi);
    cudaGetSymbolAddress((void**)&pAql, g_Aq_lo);
    cudaGetSymbolAddress((void**)&pAkh, g_Ak_hi);
    cudaGetSymbolAddress((void**)&pAkl, g_Ak_lo);
    cudaGetSymbolAddress((void**)&pAvh, g_Av_hi);
    cudaGetSymbolAddress((void**)&pAvl, g_Av_lo);
    cudaGetSymbolAddress((void**)&pWhi, g_Whi);
    cudaGetSymbolAddress((void**)&pWlo, g_Wlo);
    cudaGetSymbolAddress((void**)&pQhi, g_Qhi);
    cudaGetSymbolAddress((void**)&pQlo, g_Qlo);
    cudaGetSymbolAddress((void**)&pKhi, g_Khi);
    cudaGetSymbolAddress((void**)&pKlo, g_Klo);
    cudaGetSymbolAddress((void**)&pVthi, g_Vthi);
    cudaGetSymbolAddress((void**)&pVtlo, g_Vtlo);

    cudaFuncSetAttribute(gemm_all, cudaFuncAttributeMaxDynamicSharedMemorySize, GEMM_SMEM);
    cudaFuncSetAttribute(attn_kernel, cudaFuncAttributeMaxDynamicSharedMemorySize, ATT_SMEM);

    const int n4 = (M_TOT * HIDD) / 4;

    // 1) split q,k,v (one launch)
    cvt_act3<<<dim3(n4/256, 3), 256>>>((const float4*)q, (const float4*)k, (const float4*)v,
        (__nv_bfloat162*)pAqh, (__nv_bfloat162*)pAql,
        (__nv_bfloat162*)pAkh, (__nv_bfloat162*)pAkl,
        (__nv_bfloat162*)pAvh, (__nv_bfloat162*)pAvl, n4);

    // 2) split+transpose all 4 weights (one launch)
    cvt_wT4<<<dim3(HIDD/32, HIDD/32, 4), dim3(32, 8)>>>(Wq, Wk, Wv, Wo, pWhi, pWlo);

    // 3) Q,K,V projections fused in one launch
    gemm_all<<<dim3(HIDD/128, M_TOT/128, 3), 256, GEMM_SMEM>>>(
        pAqh, pAql, pAkh, pAkl, pAvh, pAvl, pWhi, pWlo,
        pQhi, pQlo, pKhi, pKlo, pV, nullptr, 0);

    // 4) V transpose + split
    cvt_vT<<<dim3(Ss/32, Dd/32, Bb*Hh), dim3(32, 8)>>>(pV, pVthi, pVtlo);

    // 5) attention (writes split O into pAqh/pAql)
    attn_kernel<<<dim3(Ss/ABQ, Hh, Bb), 256, ATT_SMEM>>>(
        pQhi, pQlo, pKhi, pKlo, pVthi, pVtlo, pAqh, pAql);

    // 6) output projection
    gemm_all<<<dim3(HIDD/128, M_TOT/128, 1), 256, GEMM_SMEM>>>(
        pAqh, pAql, pAkh, pAkl, pAvh, pAvl, pWhi, pWlo,
        pQhi, pQlo, pKhi, pKlo, pV, out, 1);
}

// round 6
// speedup vs baseline: 3.2339x; 1.0062x over previous
#include <cuda_runtime.h>
#include <cuda_bf16.h>
#include <cstdint>

#define Bb   4
#define Ss   2048
#define HIDD 1024
#define Hh   16
#define Dd   64
#define M_TOT (Bb*Ss)   // 8192

// ---------------- scratch (static device globals; allocation-free) ----------
__device__ float g_V[(size_t)M_TOT*HIDD];
__device__ __nv_bfloat16 g_Aq_hi[(size_t)M_TOT*HIDD];   // q split; later attn-out split
__device__ __nv_bfloat16 g_Aq_lo[(size_t)M_TOT*HIDD];
__device__ __nv_bfloat16 g_Ak_hi[(size_t)M_TOT*HIDD];
__device__ __nv_bfloat16 g_Ak_lo[(size_t)M_TOT*HIDD];
__device__ __nv_bfloat16 g_Av_hi[(size_t)M_TOT*HIDD];
__device__ __nv_bfloat16 g_Av_lo[(size_t)M_TOT*HIDD];
__device__ __nv_bfloat16 g_Whi[(size_t)4*HIDD*HIDD];    // [z][N][K], z: q,k,v,o
__device__ __nv_bfloat16 g_Wlo[(size_t)4*HIDD*HIDD];
__device__ __nv_bfloat16 g_Qhi[(size_t)M_TOT*HIDD];
__device__ __nv_bfloat16 g_Qlo[(size_t)M_TOT*HIDD];
__device__ __nv_bfloat16 g_Khi[(size_t)M_TOT*HIDD];
__device__ __nv_bfloat16 g_Klo[(size_t)M_TOT*HIDD];
__device__ __nv_bfloat16 g_Vthi[(size_t)M_TOT*HIDD];    // [b][h][d][s]
__device__ __nv_bfloat16 g_Vtlo[(size_t)M_TOT*HIDD];

// ---------------- helpers ----------------------------------------------------
__device__ __forceinline__ uint32_t smem_u32(const void* p) {
    return (uint32_t)__cvta_generic_to_shared(p);
}
#define CP16(dst,src)  asm volatile("cp.async.cg.shared.global [%0], [%1], 16;" :: "r"(dst), "l"(src) : "memory")
#define CP_COMMIT()    asm volatile("cp.async.commit_group;" ::: "memory")
#define CP_WAIT0()     asm volatile("cp.async.wait_group 0;" ::: "memory")

#define LDSM4(r0,r1,r2,r3,a) \
    asm volatile("ldmatrix.sync.aligned.m8n8.x4.shared.b16 {%0,%1,%2,%3}, [%4];" \
                 : "=r"(r0), "=r"(r1), "=r"(r2), "=r"(r3) : "r"(a))

#define MMA16816(d,a,b) \
    asm volatile("mma.sync.aligned.m16n8k16.row.col.f32.bf16.bf16.f32 " \
                 "{%0,%1,%2,%3}, {%4,%5,%6,%7}, {%8,%9}, {%0,%1,%2,%3};" \
                 : "+f"((d)[0]), "+f"((d)[1]), "+f"((d)[2]), "+f"((d)[3]) \
                 : "r"((a)[0]), "r"((a)[1]), "r"((a)[2]), "r"((a)[3]), \
                   "r"((b)[0]), "r"((b)[1]))

__device__ __forceinline__ uint32_t pack_bf2(__nv_bfloat16 a, __nv_bfloat16 b) {
    __nv_bfloat162 t = __halves2bfloat162(a, b);
    return *reinterpret_cast<uint32_t*>(&t);
}
__device__ __forceinline__ void split2(float x, float y, uint32_t& hi, uint32_t& lo) {
    __nv_bfloat16 hx = __float2bfloat16(x), hy = __float2bfloat16(y);
    __nv_bfloat16 lx = __float2bfloat16(x - __bfloat162float(hx));
    __nv_bfloat16 ly = __float2bfloat16(y - __bfloat162float(hy));
    hi = pack_bf2(hx, hy);
    lo = pack_bf2(lx, ly);
}

// ---------------- conversion kernels ----------------------------------------
__global__ __launch_bounds__(256) void cvt_act3(
    const float4* __restrict__ q, const float4* __restrict__ k, const float4* __restrict__ v,
    __nv_bfloat162* __restrict__ qh, __nv_bfloat162* __restrict__ ql,
    __nv_bfloat162* __restrict__ kh, __nv_bfloat162* __restrict__ kl,
    __nv_bfloat162* __restrict__ vh, __nv_bfloat162* __restrict__ vl, int n4)
{
    int i = blockIdx.x * blockDim.x + threadIdx.x;
    if (i >= n4) return;
    int z = blockIdx.y;
    const float4* x = (z == 0) ? q : (z == 1) ? k : v;
    __nv_bfloat162* hi = (z == 0) ? qh : (z == 1) ? kh : vh;
    __nv_bfloat162* lo = (z == 0) ? ql : (z == 1) ? kl : vl;
    float4 val = x[i];
    uint32_t h0, l0, h1, l1;
    split2(val.x, val.y, h0, l0);
    split2(val.z, val.w, h1, l1);
    hi[2*i]   = *reinterpret_cast<__nv_bfloat162*>(&h0);
    hi[2*i+1] = *reinterpret_cast<__nv_bfloat162*>(&h1);
    lo[2*i]   = *reinterpret_cast<__nv_bfloat162*>(&l0);
    lo[2*i+1] = *reinterpret_cast<__nv_bfloat162*>(&l1);
}

__global__ __launch_bounds__(256) void cvt_wT4(
    const float* __restrict__ Wq, const float* __restrict__ Wk,
    const float* __restrict__ Wv, const float* __restrict__ Wo,
    __nv_bfloat16* __restrict__ hi, __nv_bfloat16* __restrict__ lo)
{
    __shared__ float t[32][33];
    int z = blockIdx.z;
    const float* W = (z == 0) ? Wq : (z == 1) ? Wk : (z == 2) ? Wv : Wo;
    __nv_bfloat16* hz = hi + (size_t)z * HIDD * HIDD;
    __nv_bfloat16* lz = lo + (size_t)z * HIDD * HIDD;
    int n0 = blockIdx.x * 32, k0 = blockIdx.y * 32;
    int tx = threadIdx.x, ty = threadIdx.y;   // 32 x 8
    #pragma unroll
    for (int i = 0; i < 32; i += 8)
        t[ty + i][tx] = W[(size_t)(k0 + ty + i) * HIDD + n0 + tx];
    __syncthreads();
    #pragma unroll
    for (int i = 0; i < 32; i += 8) {
        float v = t[tx][ty + i];
        __nv_bfloat16 h = __float2bfloat16(v);
        __nv_bfloat16 l = __float2bfloat16(v - __bfloat162float(h));
        size_t o = (size_t)(n0 + ty + i) * HIDD + k0 + tx;
        hz[o] = h; lz[o] = l;
    }
}

__global__ __launch_bounds__(256) void cvt_vT(const float* __restrict__ V,
                                              __nv_bfloat16* __restrict__ hi,
                                              __nv_bfloat16* __restrict__ lo) {
    __shared__ float t[32][33];
    int s0 = blockIdx.x * 32, d0 = blockIdx.y * 32;
    int bh = blockIdx.z;
    int b = bh >> 4, h = bh & 15;
    int tx = threadIdx.x, ty = threadIdx.y;   // 32 x 8
    #pragma unroll
    for (int i = 0; i < 32; i += 8)
        t[ty + i][tx] = V[(size_t)(b*Ss + s0 + ty + i) * HIDD + h*Dd + d0 + tx];
    __syncthreads();
    #pragma unroll
    for (int i = 0; i < 32; i += 8) {
        float v = t[tx][ty + i];
        __nv_bfloat16 hb = __float2bfloat16(v);
        __nv_bfloat16 lb = __float2bfloat16(v - __bfloat162float(hb));
        size_t o = ((size_t)bh * Dd + d0 + ty + i) * Ss + s0 + tx;
        hi[o] = hb; lo[o] = lb;
    }
}

// ---------------- mma.sync bf16x3 GEMM v2 -----------------------------------
// CTA 128x128, 4 warps (128 threads), warp tile 64x64, BK=32, double-buffered.
// 2 CTAs/SM: one CTA's loads hide behind the other's MMA burst.
#define KTOT 1024
#define GBK  32
#define NSTG (KTOT/GBK)
#define BSTR 40
#define TILE_B (128*BSTR*2)           // 10240 B per operand tile (padded rows)
#define STG_B  (4*TILE_B)             // 40960 B per stage
#define GEMM_SMEM (2*STG_B)           // 81920 B... wait (see note): 2 stages

__global__ __launch_bounds__(128) void gemm_all(
    const __nv_bfloat16* __restrict__ Aq_hi, const __nv_bfloat16* __restrict__ Aq_lo,
    const __nv_bfloat16* __restrict__ Ak_hi, const __nv_bfloat16* __restrict__ Ak_lo,
    const __nv_bfloat16* __restrict__ Av_hi, const __nv_bfloat16* __restrict__ Av_lo,
    const __nv_bfloat16* __restrict__ Wh, const __nv_bfloat16* __restrict__ Wl,
    __nv_bfloat16* __restrict__ Qh, __nv_bfloat16* __restrict__ Ql,
    __nv_bfloat16* __restrict__ Kh, __nv_bfloat16* __restrict__ Kl,
    float* __restrict__ Vout, float* __restrict__ Final, int final_pass)
{
    extern __shared__ char smraw[];
    const uint32_t sb = smem_u32(smraw);
    const int tid = threadIdx.x;
    const int wid = tid >> 5, lane = tid & 31;
    const int m0 = blockIdx.y * 128;
    const int n0 = blockIdx.x * 128;
    const int wm = (wid & 1) * 64;       // 2 M-warps x 64 rows
    const int wn = (wid >> 1) * 64;      // 2 N-warps x 64 cols
    const int z  = final_pass ? 3 : (int)blockIdx.z;

    const __nv_bfloat16* Ahi = (z == 1) ? Ak_hi : (z == 2) ? Av_hi : Aq_hi;
    const __nv_bfloat16* Alo = (z == 1) ? Ak_lo : (z == 2) ? Av_lo : Aq_lo;
    const __nv_bfloat16* Bhi = Wh + (size_t)z * HIDD * HIDD;
    const __nv_bfloat16* Blo = Wl + (size_t)z * HIDD * HIDD;

    const char* gA_hi = (const char*)(Ahi + (size_t)m0 * KTOT);
    const char* gA_lo = (const char*)(Alo + (size_t)m0 * KTOT);
    const char* gB_hi = (const char*)(Bhi + (size_t)n0 * KTOT);
    const char* gB_lo = (const char*)(Blo + (size_t)n0 * KTOT);

    auto load_stage = [&](int it, int s) {
        const uint32_t stg = sb + (uint32_t)s * STG_B;
        const size_t kb = (size_t)it * GBK * 2;
        const char* srcs[4] = { gA_hi + kb, gA_lo + kb, gB_hi + kb, gB_lo + kb };
        #pragma unroll
        for (int op = 0; op < 4; op++) {
            const char* g = srcs[op];
            const uint32_t tb = stg + (uint32_t)op * TILE_B;
            #pragma unroll
            for (int j = 0; j < 4; j++) {
                int chunk = j * 128 + tid;      // 512 chunks = 128 rows x 4
                int r = chunk >> 2, c = chunk & 3;
                CP16(tb + (uint32_t)(r * 80 + c * 16),
                     g + (size_t)r * (KTOT * 2) + c * 16);
            }
        }
        CP_COMMIT();
    };

    const uint32_t a_off = (uint32_t)((lane & 15) * 80 + (lane >> 4) * 16);
    const uint32_t b_off = (uint32_t)((((lane >> 4) & 1) * 8 + (lane & 7)) * 80 +
                                      ((lane >> 3) & 1) * 16);

    float acc[4][8][4];
    #pragma unroll
    for (int mi = 0; mi < 4; mi++)
        #pragma unroll
        for (int ni = 0; ni < 8; ni++)
            #pragma unroll
            for (int r = 0; r < 4; r++) acc[mi][ni][r] = 0.0f;

    load_stage(0, 0);

    #pragma unroll 1
    for (int it = 0; it < NSTG; it++) {
        const int s = it & 1;
        CP_WAIT0();
        __syncthreads();
        if (it + 1 < NSTG) load_stage(it + 1, 1 - s);

        const uint32_t stg = sb + (uint32_t)s * STG_B;
        const uint32_t tAhi = stg;
        const uint32_t tAlo = stg + TILE_B;
        const uint32_t tBhi = stg + 2 * TILE_B;
        const uint32_t tBlo = stg + 3 * TILE_B;

        #pragma unroll
        for (int kk = 0; kk < 2; kk++) {
            const uint32_t koff = (uint32_t)kk * 32;
            uint32_t ah[4][4], al[4][4];
            #pragma unroll
            for (int mi = 0; mi < 4; mi++) {
                uint32_t ra = (uint32_t)((wm + mi * 16) * 80) + a_off + koff;
                LDSM4(ah[mi][0], ah[mi][1], ah[mi][2], ah[mi][3], tAhi + ra);
                LDSM4(al[mi][0], al[mi][1], al[mi][2], al[mi][3], tAlo + ra);
            }
            uint32_t bh[8][2];
            #pragma unroll
            for (int j = 0; j < 4; j++) {
                uint32_t rb = (uint32_t)((wn + j * 16) * 80) + b_off + koff;
                LDSM4(bh[2*j][0], bh[2*j][1], bh[2*j+1][0], bh[2*j+1][1], tBhi + rb);
            }
            #pragma unroll
            for (int mi = 0; mi < 4; mi++)
                #pragma unroll
                for (int ni = 0; ni < 8; ni++) MMA16816(acc[mi][ni], ah[mi], bh[ni]);
            #pragma unroll
            for (int mi = 0; mi < 4; mi++)
                #pragma unroll
                for (int ni = 0; ni < 8; ni++) MMA16816(acc[mi][ni], al[mi], bh[ni]);
            #pragma unroll
            for (int j = 0; j < 4; j++) {
                uint32_t rb = (uint32_t)((wn + j * 16) * 80) + b_off + koff;
                LDSM4(bh[2*j][0], bh[2*j][1], bh[2*j+1][0], bh[2*j+1][1], tBlo + rb);
            }
            #pragma unroll
            for (int mi = 0; mi < 4; mi++)
                #pragma unroll
                for (int ni = 0; ni < 8; ni++) MMA16816(acc[mi][ni], ah[mi], bh[ni]);
        }
        __syncthreads();
    }

    const int r_in = lane >> 2;
    const int c_in = (lane & 3) * 2;
    __nv_bfloat16* Chi = (z == 0) ? Qh : Kh;
    __nv_bfloat16* Clo = (z == 0) ? Ql : Kl;
    float* Cf = (z == 2) ? Vout : Final;
    #pragma unroll
    for (int mi = 0; mi < 4; mi++) {
        #pragma unroll
        for (int ni = 0; ni < 8; ni++) {
            size_t o0 = (size_t)(m0 + wm + mi * 16 + r_in) * HIDD + n0 + wn + ni * 8 + c_in;
            size_t o1 = o0 + 8 * HIDD;
            if (z < 2) {
                uint32_t h, l;
                split2(acc[mi][ni][0], acc[mi][ni][1], h, l);
                *(uint32_t*)(Chi + o0) = h; *(uint32_t*)(Clo + o0) = l;
                split2(acc[mi][ni][2], acc[mi][ni][3], h, l);
                *(uint32_t*)(Chi + o1) = h; *(uint32_t*)(Clo + o1) = l;
            } else {
                *(float2*)(Cf + o0) = make_float2(acc[mi][ni][0], acc[mi][ni][1]);
                *(float2*)(Cf + o1) = make_float2(acc[mi][ni][2], acc[mi][ni][3]);
            }
        }
    }
}

// ---------------- tensor-core flash attention (bf16x3, unchanged) -----------
#define ABQ 128
#define ABK 64
#define ASTR 144
#define SQH 0
#define SQL (128*ASTR)
#define SQTOT (2*128*ASTR)
#define AOFF_KH 0
#define AOFF_KL (64*ASTR)
#define AOFF_VH (2*64*ASTR)
#define AOFF_VL (3*64*ASTR)
#define ASTG_B (4*64*ASTR)
#define ATT_SMEM (SQTOT + 2*ASTG_B)

__global__ __launch_bounds__(256) void attn_kernel(
    const __nv_bfloat16* __restrict__ Qhi, const __nv_bfloat16* __restrict__ Qlo,
    const __nv_bfloat16* __restrict__ Khi, const __nv_bfloat16* __restrict__ Klo,
    const __nv_bfloat16* __restrict__ Vthi, const __nv_bfloat16* __restrict__ Vtlo,
    __nv_bfloat16* __restrict__ Ohi, __nv_bfloat16* __restrict__ Olo)
{
    extern __shared__ char smraw[];
    const uint32_t sb = smem_u32(smraw);
    const int tid = threadIdx.x;
    const int wid = tid >> 5, lane = tid & 31;
    const int q0 = blockIdx.x * ABQ;
    const int h  = blockIdx.y;
    const int b  = blockIdx.z;
    const int wm = wid * 16;

    const char* qh_base = (const char*)(Qhi + (size_t)(b*Ss + q0)*HIDD + h*Dd);
    const char* ql_base = (const char*)(Qlo + (size_t)(b*Ss + q0)*HIDD + h*Dd);
    const char* kh_base = (const char*)(Khi + (size_t)(b*Ss)*HIDD + h*Dd);
    const char* kl_base = (const char*)(Klo + (size_t)(b*Ss)*HIDD + h*Dd);
    const char* vh_base = (const char*)(Vthi + ((size_t)(b*Hh + h)*Dd)*Ss);
    const char* vl_base = (const char*)(Vtlo + ((size_t)(b*Hh + h)*Dd)*Ss);

    #pragma unroll
    for (int j = 0; j < 4; j++) {
        int idx = j * 256 + tid;
        int r = idx >> 3, c = idx & 7;
        CP16(sb + SQH + (uint32_t)(r*ASTR + c*16), qh_base + (size_t)r*2048 + c*16);
        CP16(sb + SQL + (uint32_t)(r*ASTR + c*16), ql_base + (size_t)r*2048 + c*16);
    }
    auto load_stage = [&](int kt, int s) {
        const uint32_t stg = sb + SQTOT + (uint32_t)s * ASTG_B;
        const size_t krow = (size_t)kt * ABK;
        #pragma unroll
        for (int j = 0; j < 2; j++) {
            int idx = j * 256 + tid;
            int r = idx >> 3, c = idx & 7;
            uint32_t so = (uint32_t)(r*ASTR + c*16);
            CP16(stg + AOFF_KH + so, kh_base + (krow + r)*2048 + c*16);
            CP16(stg + AOFF_KL + so, kl_base + (krow + r)*2048 + c*16);
            CP16(stg + AOFF_VH + so, vh_base + (size_t)r*4096 + krow*2 + c*16);
            CP16(stg + AOFF_VL + so, vl_base + (size_t)r*4096 + krow*2 + c*16);
        }
    };
    load_stage(0, 0);
    CP_COMMIT();

    const uint32_t a_off = (uint32_t)((lane & 15) * ASTR + (lane >> 4) * 16);
    const uint32_t b_off = (uint32_t)((((lane >> 4) & 1) * 8 + (lane & 7)) * ASTR +
                                      ((lane >> 3) & 1) * 16);

    uint32_t ah[4][4], al[4][4];
    float oacc[8][4];
    #pragma unroll
    for (int j = 0; j < 8; j++)
        #pragma unroll
        for (int r = 0; r < 4; r++) oacc[j][r] = 0.0f;
    float m0 = -1e30f, m1 = -1e30f, l0 = 0.0f, l1 = 0.0f;
    const float csc = 0.125f * 1.44269504088896340736f;

    #pragma unroll 1
    for (int it = 0; it < Ss/ABK; it++) {
        const int s = it & 1;
        CP_WAIT0();
        __syncthreads();
        if (it == 0) {
            #pragma unroll
            for (int kk = 0; kk < 4; kk++) {
                uint32_t ra = (uint32_t)(wm * ASTR) + a_off + kk * 32;
                LDSM4(ah[kk][0], ah[kk][1], ah[kk][2], ah[kk][3], sb + SQH + ra);
                LDSM4(al[kk][0], al[kk][1], al[kk][2], al[kk][3], sb + SQL + ra);
            }
        }
        if (it + 1 < Ss/ABK) { load_stage(it + 1, 1 - s); CP_COMMIT(); }

        const uint32_t stg = sb + SQTOT + (uint32_t)s * ASTG_B;

        float sacc[8][4];
        #pragma unroll
        for (int j = 0; j < 8; j++)
            #pragma unroll
            for (int r = 0; r < 4; r++) sacc[j][r] = 0.0f;
        #pragma unroll
        for (int kk = 0; kk < 4; kk++) {
            uint32_t bh[8][2], bl[8][2];
            #pragma unroll
            for (int j = 0; j < 4; j++) {
                uint32_t rb = (uint32_t)(j * 16 * ASTR) + b_off + kk * 32;
                LDSM4(bh[2*j][0], bh[2*j][1], bh[2*j+1][0], bh[2*j+1][1], stg + AOFF_KH + rb);
                LDSM4(bl[2*j][0], bl[2*j][1], bl[2*j+1][0], bl[2*j+1][1], stg + AOFF_KL + rb);
            }
            #pragma unroll
            for (int j = 0; j < 8; j++) MMA16816(sacc[j], ah[kk], bh[j]);
            #pragma unroll
            for (int j = 0; j < 8; j++) MMA16816(sacc[j], al[kk], bh[j]);
            #pragma unroll
            for (int j = 0; j < 8; j++) MMA16816(sacc[j], ah[kk], bl[j]);
        }

        float mx0 = -1e30f, mx1 = -1e30f;
        #pragma unroll
        for (int j = 0; j < 8; j++) {
            mx0 = fmaxf(mx0, fmaxf(sacc[j][0], sacc[j][1]));
            mx1 = fmaxf(mx1, fmaxf(sacc[j][2], sacc[j][3]));
        }
        mx0 = fmaxf(mx0, __shfl_xor_sync(0xffffffffu, mx0, 1));
        mx0 = fmaxf(mx0, __shfl_xor_sync(0xffffffffu, mx0, 2));
        mx1 = fmaxf(mx1, __shfl_xor_sync(0xffffffffu, mx1, 1));
        mx1 = fmaxf(mx1, __shfl_xor_sync(0xffffffffu, mx1, 2));
        mx0 *= csc; mx1 *= csc;
        float nm0 = fmaxf(m0, mx0), nm1 = fmaxf(m1, mx1);
        float a0 = exp2f(m0 - nm0), a1 = exp2f(m1 - nm1);
        m0 = nm0; m1 = nm1;

        float sum0 = 0.0f, sum1 = 0.0f;
        #pragma unroll
        for (int j = 0; j < 8; j++) {
            sacc[j][0] = exp2f(fmaf(sacc[j][0], csc, -nm0));
            sacc[j][1] = exp2f(fmaf(sacc[j][1], csc, -nm0));
            sacc[j][2] = exp2f(fmaf(sacc[j][2], csc, -nm1));
            sacc[j][3] = exp2f(fmaf(sacc[j][3], csc, -nm1));
            sum0 += sacc[j][0] + sacc[j][1];
            sum1 += sacc[j][2] + sacc[j][3];
        }
        sum0 += __shfl_xor_sync(0xffffffffu, sum0, 1);
        sum0 += __shfl_xor_sync(0xffffffffu, sum0, 2);
        sum1 += __shfl_xor_sync(0xffffffffu, sum1, 1);
        sum1 += __shfl_xor_sync(0xffffffffu, sum1, 2);
        l0 = l0 * a0 + sum0;
        l1 = l1 * a1 + sum1;
        #pragma unroll
        for (int j = 0; j < 8; j++) {
            oacc[j][0] *= a0; oacc[j][1] *= a0;
            oacc[j][2] *= a1; oacc[j][3] *= a1;
        }

        #pragma unroll
        for (int kk = 0; kk < 4; kk++) {
            uint32_t pah[4], pal[4];
            split2(sacc[2*kk][0],   sacc[2*kk][1],   pah[0], pal[0]);
            split2(sacc[2*kk][2],   sacc[2*kk][3],   pah[1], pal[1]);
            split2(sacc[2*kk+1][0], sacc[2*kk+1][1], pah[2], pal[2]);
            split2(sacc[2*kk+1][2], sacc[2*kk+1][3], pah[3], pal[3]);

            uint32_t bh[8][2], bl[8][2];
            #pragma unroll
            for (int j = 0; j < 4; j++) {
                uint32_t rb = (uint32_t)(j * 16 * ASTR) + b_off + kk * 32;
                LDSM4(bh[2*j][0], bh[2*j][1], bh[2*j+1][0], bh[2*j+1][1], stg + AOFF_VH + rb);
                LDSM4(bl[2*j][0], bl[2*j][1], bl[2*j+1][0], bl[2*j+1][1], stg + AOFF_VL + rb);
            }
            #pragma unroll
            for (int j = 0; j < 8; j++) MMA16816(oacc[j], pah, bh[j]);
            #pragma unroll
            for (int j = 0; j < 8; j++) MMA16816(oacc[j], pal, bh[j]);
            #pragma unroll
            for (int j = 0; j < 8; j++) MMA16816(oacc[j], pah, bl[j]);
        }
        __syncthreads();
    }

    const float inv0 = 1.0f / l0, inv1 = 1.0f / l1;
    const int r0 = lane >> 2;
    const size_t row0 = (size_t)(b*Ss + q0 + wm + r0) * HIDD + h*Dd + (lane & 3) * 2;
    const size_t row1 = row0 + 8 * HIDD;
    #pragma unroll
    for (int j = 0; j < 8; j++) {
        uint32_t hh, ll;
        split2(oacc[j][0] * inv0, oacc[j][1] * inv0, hh, ll);
        *(uint32_t*)(Ohi + row0 + j*8) = hh;
        *(uint32_t*)(Olo + row0 + j*8) = ll;
        split2(oacc[j][2] * inv1, oacc[j][3] * inv1, hh, ll);
        *(uint32_t*)(Ohi + row1 + j*8) = hh;
        *(uint32_t*)(Olo + row1 + j*8) = ll;
    }
}

// ---------------------------------------------------------------------------
extern "C" void kernel_launch(void* const* d_in, const int* in_sizes, int n_in,
                              void* d_out, int out_size)
{
    (void)in_sizes; (void)n_in; (void)out_size;
    const float* q  = (const float*)d_in[0];
    const float* k  = (const float*)d_in[1];
    const float* v  = (const float*)d_in[2];
    const float* Wq = (const float*)d_in[3];
    const float* Wk = (const float*)d_in[4];
    const float* Wv = (const float*)d_in[5];
    const float* Wo = (const float*)d_in[6];
    float* out = (float*)d_out;

    float *pV;
    __nv_bfloat16 *pAqh, *pAql, *pAkh, *pAkl, *pAvh, *pAvl;
    __nv_bfloat16 *pWhi, *pWlo, *pQhi, *pQlo, *pKhi, *pKlo, *pVthi, *pVtlo;
    cudaGetSymbolAddress((void**)&pV, g_V);
    cudaGetSymbolAddress((void**)&pAqh, g_Aq_hi);
    cudaGetSymbolAddress((void**)&pAql, g_Aq_lo);
    cudaGetSymbolAddress((void**)&pAkh, g_Ak_hi);
    cudaGetSymbolAddress((void**)&pAkl, g_Ak_lo);
    cudaGetSymbolAddress((void**)&pAvh, g_Av_hi);
    cudaGetSymbolAddress((void**)&pAvl, g_Av_lo);
    cudaGetSymbolAddress((void**)&pWhi, g_Whi);
    cudaGetSymbolAddress((void**)&pWlo, g_Wlo);
    cudaGetSymbolAddress((void**)&pQhi, g_Qhi);
    cudaGetSymbolAddress((void**)&pQlo, g_Qlo);
    cudaGetSymbolAddress((void**)&pKhi, g_Khi);
    cudaGetSymbolAddress((void**)&pKlo, g_Klo);
    cudaGetSymbolAddress((void**)&pVthi, g_Vthi);
    cudaGetSymbolAddress((void**)&pVtlo, g_Vtlo);

    cudaFuncSetAttribute(gemm_all, cudaFuncAttributeMaxDynamicSharedMemorySize, GEMM_SMEM);
    cudaFuncSetAttribute(attn_kernel, cudaFuncAttributeMaxDynamicSharedMemorySize, ATT_SMEM);

    const int n4 = (M_TOT * HIDD) / 4;

    // 1) split q,k,v (one launch)
    cvt_act3<<<dim3(n4/256, 3), 256>>>((const float4*)q, (const float4*)k, (const float4*)v,
        (__nv_bfloat162*)pAqh, (__nv_bfloat162*)pAql,
        (__nv_bfloat162*)pAkh, (__nv_bfloat162*)pAkl,
        (__nv_bfloat162*)pAvh, (__nv_bfloat162*)pAvl, n4);

    // 2) split+transpose all 4 weights (one launch)
    cvt_wT4<<<dim3(HIDD/32, HIDD/32, 4), dim3(32, 8)>>>(Wq, Wk, Wv, Wo, pWhi, pWlo);

    // 3) Q,K,V projections fused in one launch
    gemm_all<<<dim3(HIDD/128, M_TOT/128, 3), 128, GEMM_SMEM>>>(
        pAqh, pAql, pAkh, pAkl, pAvh, pAvl, pWhi, pWlo,
        pQhi, pQlo, pKhi, pKlo, pV, nullptr, 0);

    // 4) V transpose + split
    cvt_vT<<<dim3(Ss/32, Dd/32, Bb*Hh), dim3(32, 8)>>>(pV, pVthi, pVtlo);

    // 5) attention (writes split O into pAqh/pAql)
    attn_kernel<<<dim3(Ss/ABQ, Hh, Bb), 256, ATT_SMEM>>>(
        pQhi, pQlo, pKhi, pKlo, pVthi, pVtlo, pAqh, pAql);

    // 6) output projection
    gemm_all<<<dim3(HIDD/128, M_TOT/128, 1), 128, GEMM_SMEM>>>(
        pAqh, pAql, pAkh, pAkl, pAvh, pAvl, pWhi, pWlo,
        pQhi, pQlo, pKhi, pKlo, pV, out, 1);
}